// round 1
// baseline (speedup 1.0000x reference)
#include <cuda_runtime.h>
#include <cstdint>

#define D_H      128
#define D_IN     64
#define N_U      100000
#define N_I      50000
#define N_LAYERS 2
#define SLOPE_F  0.2f
#define EPS_F    1e-5f

// ---------------- scratch (static device globals; no runtime allocation) ----
__device__ __align__(256) float g_u [(size_t)N_U * D_H];   // user features
__device__ __align__(256) float g_i [(size_t)N_I * D_H];   // item features
__device__ __align__(256) float g_tA[(size_t)N_U * D_H];   // spmm accum (y1/y2)
__device__ __align__(256) float g_tB[(size_t)N_U * D_H];   // lat1

__device__ __forceinline__ float leakyf(float x) { return x > 0.f ? x : SLOPE_F * x; }

// ---------------- utility kernels -------------------------------------------
__global__ void zero_f4(float4* __restrict__ p, int n4) {
    int i = blockIdx.x * blockDim.x + threadIdx.x;
    int stride = gridDim.x * blockDim.x;
    float4 z = make_float4(0.f, 0.f, 0.f, 0.f);
    for (; i < n4; i += stride) p[i] = z;
}

__global__ void scale_f4(float4* __restrict__ p, int n4, float s) {
    int i = blockIdx.x * blockDim.x + threadIdx.x;
    int stride = gridDim.x * blockDim.x;
    for (; i < n4; i += stride) {
        float4 v = p[i];
        v.x *= s; v.y *= s; v.z *= s; v.w *= s;
        p[i] = v;
    }
}

// ---------------- FC + LeakyReLU: out[j] = leaky(dot(emb_row, W[j,:]) + b[j])
// Writes the same row to out1 (feature buffer) and out2 (acc / d_out region).
__global__ void fc_leaky_kernel(const float* __restrict__ emb,
                                const float* __restrict__ W,   // [D_H, D_IN]
                                const float* __restrict__ b,
                                float* __restrict__ out1,
                                float* __restrict__ out2,
                                int nrows) {
    __shared__ float sWt[D_IN * D_H];  // transposed: sWt[k*128 + j] = W[j*64 + k]
    __shared__ float sX[4][D_IN];
    const int j = threadIdx.x;  // 0..127
    for (int idx = j; idx < D_IN * D_H; idx += D_H) {
        int k = idx >> 7, jj = idx & 127;
        sWt[idx] = W[jj * D_IN + k];
    }
    const float bj = b[j];
    __syncthreads();

    for (int rbase = blockIdx.x * 4; rbase < nrows; rbase += gridDim.x * 4) {
        for (int t = j; t < 4 * D_IN; t += D_H) {
            int rr = t >> 6, kk = t & 63;
            int row = rbase + rr;
            sX[rr][kk] = (row < nrows) ? emb[(size_t)row * D_IN + kk] : 0.f;
        }
        __syncthreads();
        float a0 = bj, a1 = bj, a2 = bj, a3 = bj;
        #pragma unroll 8
        for (int k = 0; k < D_IN; k++) {
            float w = sWt[k * D_H + j];
            a0 += w * sX[0][k];
            a1 += w * sX[1][k];
            a2 += w * sX[2][k];
            a3 += w * sX[3][k];
        }
        a0 = leakyf(a0); a1 = leakyf(a1); a2 = leakyf(a2); a3 = leakyf(a3);
        if (rbase + 0 < nrows) { out1[(size_t)(rbase+0)*D_H + j] = a0; out2[(size_t)(rbase+0)*D_H + j] = a0; }
        if (rbase + 1 < nrows) { out1[(size_t)(rbase+1)*D_H + j] = a1; out2[(size_t)(rbase+1)*D_H + j] = a1; }
        if (rbase + 2 < nrows) { out1[(size_t)(rbase+2)*D_H + j] = a2; out2[(size_t)(rbase+2)*D_H + j] = a2; }
        if (rbase + 3 < nrows) { out1[(size_t)(rbase+3)*D_H + j] = a3; out2[(size_t)(rbase+3)*D_H + j] = a3; }
        __syncthreads();
    }
}

// ---------------- SpMM: y[dst[e], :] += vals[e] * x[src[e], :]  --------------
// One warp processes 32 edges per batch: coalesced index loads, then per edge
// the full warp does one float4 gather + one red.global.add.v4.f32 scatter.
__global__ void spmm_kernel(const int*   __restrict__ dst,
                            const int*   __restrict__ src,
                            const float* __restrict__ vals,
                            const float* __restrict__ x,
                            float*       __restrict__ y,
                            int nnz) {
    const int lane = threadIdx.x & 31;
    int warp  = (blockIdx.x * blockDim.x + threadIdx.x) >> 5;
    int nwarp = (gridDim.x * blockDim.x) >> 5;
    for (int base = warp * 32; base < nnz; base += nwarp * 32) {
        int e = base + lane;
        int d = -1, s = 0;
        float v = 0.f;
        if (e < nnz) { d = dst[e]; s = src[e]; v = vals[e]; }
        #pragma unroll 4
        for (int jj = 0; jj < 32; jj++) {
            int dj = __shfl_sync(0xffffffffu, d, jj);
            if (dj < 0) break;
            int   sj = __shfl_sync(0xffffffffu, s, jj);
            float vj = __shfl_sync(0xffffffffu, v, jj);
            float4 xv = __ldg(reinterpret_cast<const float4*>(x + (size_t)sj * D_H) + lane);
            xv.x *= vj; xv.y *= vj; xv.z *= vj; xv.w *= vj;
            float* yp = y + (size_t)dj * D_H + lane * 4;
            asm volatile("red.global.add.v4.f32 [%0], {%1, %2, %3, %4};"
                         :: "l"(yp), "f"(xv.x), "f"(xv.y), "f"(xv.z), "f"(xv.w)
                         : "memory");
        }
    }
}

// ---------------- GEMM (X @ W^T) + LayerNorm: out = LN(X @ W.T) * g + b ------
// 128 threads/block, W transposed in dynamic shared (conflict-free), 4 rows/iter.
__global__ void gemm_ln_kernel(const float* __restrict__ X,   // [nrows, 128]
                               const float* __restrict__ W,   // [128, 128]
                               const float* __restrict__ g,
                               const float* __restrict__ b,
                               float* __restrict__ out,
                               int nrows) {
    extern __shared__ float sWt[];     // D_H*D_H floats: sWt[k*128+j] = W[j*128+k]
    __shared__ float sX[4][D_H];
    __shared__ float sSum[4][4];
    __shared__ float sSq[4][4];
    const int j = threadIdx.x;
    const int w = j >> 5, lane = j & 31;

    for (int idx = j; idx < D_H * D_H; idx += D_H)
        sWt[idx] = W[(idx & 127) * D_H + (idx >> 7)];
    const float gj = g[j];
    const float bj = b[j];
    __syncthreads();

    for (int rbase = blockIdx.x * 4; rbase < nrows; rbase += gridDim.x * 4) {
        #pragma unroll
        for (int t = 0; t < 4; t++) {
            int row = rbase + t;
            sX[t][j] = (row < nrows) ? X[(size_t)row * D_H + j] : 0.f;
        }
        __syncthreads();
        float a0 = 0.f, a1 = 0.f, a2 = 0.f, a3 = 0.f;
        #pragma unroll 8
        for (int k = 0; k < D_H; k++) {
            float ww = sWt[k * D_H + j];
            a0 += ww * sX[0][k];
            a1 += ww * sX[1][k];
            a2 += ww * sX[2][k];
            a3 += ww * sX[3][k];
        }
        // block-wide mean / var per row
        float s0 = a0, s1 = a1, s2 = a2, s3 = a3;
        float q0 = a0*a0, q1 = a1*a1, q2 = a2*a2, q3 = a3*a3;
        #pragma unroll
        for (int off = 16; off; off >>= 1) {
            s0 += __shfl_xor_sync(0xffffffffu, s0, off);
            s1 += __shfl_xor_sync(0xffffffffu, s1, off);
            s2 += __shfl_xor_sync(0xffffffffu, s2, off);
            s3 += __shfl_xor_sync(0xffffffffu, s3, off);
            q0 += __shfl_xor_sync(0xffffffffu, q0, off);
            q1 += __shfl_xor_sync(0xffffffffu, q1, off);
            q2 += __shfl_xor_sync(0xffffffffu, q2, off);
            q3 += __shfl_xor_sync(0xffffffffu, q3, off);
        }
        if (lane == 0) {
            sSum[0][w] = s0; sSum[1][w] = s1; sSum[2][w] = s2; sSum[3][w] = s3;
            sSq [0][w] = q0; sSq [1][w] = q1; sSq [2][w] = q2; sSq [3][w] = q3;
        }
        __syncthreads();
        const float inv = 1.f / (float)D_H;
        float mu0 = (sSum[0][0]+sSum[0][1]+sSum[0][2]+sSum[0][3]) * inv;
        float mu1 = (sSum[1][0]+sSum[1][1]+sSum[1][2]+sSum[1][3]) * inv;
        float mu2 = (sSum[2][0]+sSum[2][1]+sSum[2][2]+sSum[2][3]) * inv;
        float mu3 = (sSum[3][0]+sSum[3][1]+sSum[3][2]+sSum[3][3]) * inv;
        float rs0 = rsqrtf((sSq[0][0]+sSq[0][1]+sSq[0][2]+sSq[0][3]) * inv - mu0*mu0 + EPS_F);
        float rs1 = rsqrtf((sSq[1][0]+sSq[1][1]+sSq[1][2]+sSq[1][3]) * inv - mu1*mu1 + EPS_F);
        float rs2 = rsqrtf((sSq[2][0]+sSq[2][1]+sSq[2][2]+sSq[2][3]) * inv - mu2*mu2 + EPS_F);
        float rs3 = rsqrtf((sSq[3][0]+sSq[3][1]+sSq[3][2]+sSq[3][3]) * inv - mu3*mu3 + EPS_F);
        if (rbase + 0 < nrows) out[(size_t)(rbase+0)*D_H + j] = (a0 - mu0) * rs0 * gj + bj;
        if (rbase + 1 < nrows) out[(size_t)(rbase+1)*D_H + j] = (a1 - mu1) * rs1 * gj + bj;
        if (rbase + 2 < nrows) out[(size_t)(rbase+2)*D_H + j] = (a2 - mu2) * rs2 * gj + bj;
        if (rbase + 3 < nrows) out[(size_t)(rbase+3)*D_H + j] = (a3 - mu3) * rs3 * gj + bj;
        __syncthreads();
    }
}

// ---------------- LN + leaky + residual/accumulator update -------------------
// h = leaky(LN(y)*g+b);  feat += h;  acc += h.   One warp per row.
__global__ void ln_leaky_update_kernel(const float* __restrict__ y,
                                       const float* __restrict__ g,
                                       const float* __restrict__ b,
                                       float* __restrict__ feat,
                                       float* __restrict__ acc,
                                       int nrows) {
    const int lane = threadIdx.x & 31;
    int row  = (blockIdx.x * blockDim.x + threadIdx.x) >> 5;
    int nw   = (gridDim.x * blockDim.x) >> 5;
    const float4 gv = *(reinterpret_cast<const float4*>(g) + lane);
    const float4 bv = *(reinterpret_cast<const float4*>(b) + lane);
    for (; row < nrows; row += nw) {
        float4 v = __ldg(reinterpret_cast<const float4*>(y + (size_t)row * D_H) + lane);
        float s = v.x + v.y + v.z + v.w;
        float q = v.x*v.x + v.y*v.y + v.z*v.z + v.w*v.w;
        #pragma unroll
        for (int off = 16; off; off >>= 1) {
            s += __shfl_xor_sync(0xffffffffu, s, off);
            q += __shfl_xor_sync(0xffffffffu, q, off);
        }
        const float inv = 1.f / (float)D_H;
        float mu = s * inv;
        float rs = rsqrtf(q * inv - mu * mu + EPS_F);
        float4 h;
        h.x = leakyf((v.x - mu) * rs * gv.x + bv.x);
        h.y = leakyf((v.y - mu) * rs * gv.y + bv.y);
        h.z = leakyf((v.z - mu) * rs * gv.z + bv.z);
        h.w = leakyf((v.w - mu) * rs * gv.w + bv.w);
        float4* fp = reinterpret_cast<float4*>(feat + (size_t)row * D_H) + lane;
        float4 fv = *fp;
        fv.x += h.x; fv.y += h.y; fv.z += h.z; fv.w += h.w;
        *fp = fv;
        float4* ap = reinterpret_cast<float4*>(acc + (size_t)row * D_H) + lane;
        float4 av = *ap;
        av.x += h.x; av.y += h.y; av.z += h.z; av.w += h.w;
        *ap = av;
    }
}

// ---------------- launch ------------------------------------------------------
static inline void launch_zero(float* p, int nfloats) {
    int n4 = nfloats >> 2;
    int blocks = (n4 + 255) / 256;
    if (blocks > 8192) blocks = 8192;
    zero_f4<<<blocks, 256>>>(reinterpret_cast<float4*>(p), n4);
}

extern "C" void kernel_launch(void* const* d_in, const int* in_sizes, int n_in,
                              void* d_out, int out_size) {
    const float* emb     = (const float*)d_in[0];
    const float* fc_u_w  = (const float*)d_in[1];
    const float* fc_u_b  = (const float*)d_in[2];
    const float* fc_i_w  = (const float*)d_in[3];
    const float* fc_i_b  = (const float*)d_in[4];
    const float* vals    = (const float*)d_in[5];
    const float* Wu      = (const float*)d_in[6];
    const float* ln1g_u  = (const float*)d_in[7];
    const float* ln1b_u  = (const float*)d_in[8];
    const float* ln2g_u  = (const float*)d_in[9];
    const float* ln2b_u  = (const float*)d_in[10];
    const float* Wi      = (const float*)d_in[11];
    const float* ln1g_i  = (const float*)d_in[12];
    const float* ln1b_i  = (const float*)d_in[13];
    const float* ln2g_i  = (const float*)d_in[14];
    const float* ln2b_i  = (const float*)d_in[15];
    const int*   rows    = (const int*)d_in[16];
    const int*   cols    = (const int*)d_in[17];
    float* out = (float*)d_out;
    const int nnz = in_sizes[5];
    (void)n_in; (void)out_size;

    float *pu, *pi, *tA, *tB;
    cudaGetSymbolAddress((void**)&pu, g_u);
    cudaGetSymbolAddress((void**)&pi, g_i);
    cudaGetSymbolAddress((void**)&tA, g_tA);
    cudaGetSymbolAddress((void**)&tB, g_tB);

    cudaFuncSetAttribute(gemm_ln_kernel,
                         cudaFuncAttributeMaxDynamicSharedMemorySize,
                         D_H * D_H * (int)sizeof(float));

    const int GL_BLOCKS  = 1480;                 // gemm/fc persistent-ish grids
    const int SPMM_BLOCKS = (nnz + 255) / 256;   // 8 warps * 32 edges per block
    const size_t GLN = D_H * D_H * sizeof(float);

    // initial projections: u, i, and acc(=d_out) initialization
    fc_leaky_kernel<<<GL_BLOCKS, D_H>>>(emb, fc_u_w, fc_u_b, pu, out, N_U);
    fc_leaky_kernel<<<GL_BLOCKS, D_H>>>(emb + (size_t)N_U * D_IN, fc_i_w, fc_i_b,
                                        pi, out + (size_t)N_U * D_H, N_I);

    for (int k = 0; k < N_LAYERS; k++) {
        const float* Wu_k   = Wu     + (size_t)k * D_H * D_H;
        const float* Wi_k   = Wi     + (size_t)k * D_H * D_H;
        // ---- hu: y1[i] = A^T u ; lat1 = LN(y1 Wu^T) ; y2[u] = A lat1 ; update u
        launch_zero(tA, N_I * D_H);
        spmm_kernel<<<SPMM_BLOCKS, 256>>>(cols, rows, vals, pu, tA, nnz);
        gemm_ln_kernel<<<GL_BLOCKS, D_H, GLN>>>(tA, Wu_k,
                                                ln1g_u + k * D_H, ln1b_u + k * D_H,
                                                tB, N_I);
        launch_zero(tA, N_U * D_H);
        spmm_kernel<<<SPMM_BLOCKS, 256>>>(rows, cols, vals, tB, tA, nnz);
        ln_leaky_update_kernel<<<(N_U + 7) / 8, 256>>>(tA,
                                                       ln2g_u + k * D_H, ln2b_u + k * D_H,
                                                       pu, out, N_U);
        // ---- hi: y1[u] = A i ; lat1 = LN(y1 Wi^T) ; y2[i] = A^T lat1 ; update i
        launch_zero(tA, N_U * D_H);
        spmm_kernel<<<SPMM_BLOCKS, 256>>>(rows, cols, vals, pi, tA, nnz);
        gemm_ln_kernel<<<GL_BLOCKS, D_H, GLN>>>(tA, Wi_k,
                                                ln1g_i + k * D_H, ln1b_i + k * D_H,
                                                tB, N_U);
        launch_zero(tA, N_I * D_H);
        spmm_kernel<<<SPMM_BLOCKS, 256>>>(cols, rows, vals, tB, tA, nnz);
        ln_leaky_update_kernel<<<(N_I + 7) / 8, 256>>>(tA,
                                                       ln2g_i + k * D_H, ln2b_i + k * D_H,
                                                       pi, out + (size_t)N_U * D_H, N_I);
    }

    // all_emb = acc / (L+1)
    {
        int n4 = ((N_U + N_I) * D_H) >> 2;
        int blocks = (n4 + 255) / 256;
        if (blocks > 8192) blocks = 8192;
        scale_f4<<<blocks, 256>>>(reinterpret_cast<float4*>(out), n4, 1.f / 3.f);
    }
}

// round 2
// speedup vs baseline: 1.5822x; 1.5822x over previous
#include <cuda_runtime.h>
#include <cstdint>

#define D_H      128
#define D_IN     64
#define N_U      100000
#define N_I      50000
#define NNZ_MAX  5000000
#define N_LAYERS 2
#define SLOPE_F  0.2f
#define EPS_F    1e-5f

// ---------------- scratch (static device globals; no runtime allocation) ----
__device__ __align__(256) float g_u [(size_t)N_U * D_H];   // user features
__device__ __align__(256) float g_i [(size_t)N_I * D_H];   // item features
__device__ __align__(256) float g_tA[(size_t)N_U * D_H];   // spmm out (y1/y2)
__device__ __align__(256) float g_tB[(size_t)N_U * D_H];   // lat1

// CSR structures, two directions.
// byU: key = rows (dst user), payload = (cols, val)
// byI: key = cols (dst item), payload = (rows, val)
__device__ __align__(256) int2 g_edgeU[NNZ_MAX];
__device__ __align__(256) int2 g_edgeI[NNZ_MAX];
__device__ int g_ptrU[N_U + 1];
__device__ int g_ptrI[N_I + 1];
__device__ int g_posU[N_U];
__device__ int g_posI[N_I];
__device__ int g_cntU[N_U];
__device__ int g_cntI[N_I];

__device__ __forceinline__ float leakyf(float x) { return x > 0.f ? x : SLOPE_F * x; }

// ---------------- CSR build kernels ------------------------------------------
__global__ void zero_int2arr(int* __restrict__ a, int na, int* __restrict__ b, int nb) {
    int i = blockIdx.x * blockDim.x + threadIdx.x;
    int stride = gridDim.x * blockDim.x;
    for (; i < na; i += stride) a[i] = 0;
    for (i = blockIdx.x * blockDim.x + threadIdx.x; i < nb; i += stride) b[i] = 0;
}

__global__ void hist_kernel(const int* __restrict__ keysA, int* __restrict__ cntA,
                            const int* __restrict__ keysB, int* __restrict__ cntB,
                            int nnz) {
    int i = blockIdx.x * blockDim.x + threadIdx.x;
    int stride = gridDim.x * blockDim.x;
    for (; i < nnz; i += stride) {
        atomicAdd(&cntA[keysA[i]], 1);
        atomicAdd(&cntB[keysB[i]], 1);
    }
}

// single-block exclusive scan: ptr[0]=0, ptr[i+1]=sum cnt[0..i]; pos[i]=ptr[i]
__global__ void scan_kernel(const int* __restrict__ cnt, int* __restrict__ ptr,
                            int* __restrict__ pos, int n) {
    __shared__ int sdata[1024];
    __shared__ int sCarry;
    const int tid = threadIdx.x;
    if (tid == 0) { sCarry = 0; ptr[0] = 0; }
    __syncthreads();
    for (int base = 0; base < n; base += 1024) {
        int i = base + tid;
        int v = (i < n) ? cnt[i] : 0;
        sdata[tid] = v;
        __syncthreads();
        #pragma unroll
        for (int off = 1; off < 1024; off <<= 1) {
            int t = (tid >= off) ? sdata[tid - off] : 0;
            __syncthreads();
            sdata[tid] += t;
            __syncthreads();
        }
        if (i < n) {
            int excl = sCarry + sdata[tid] - v;
            ptr[i + 1] = sCarry + sdata[tid];
            pos[i] = excl;
        }
        __syncthreads();
        if (tid == 0) sCarry += sdata[1023];
        __syncthreads();
    }
}

__global__ void build_kernel(const int* __restrict__ keys,
                             const int* __restrict__ other,
                             const float* __restrict__ vals,
                             int* __restrict__ pos,
                             int2* __restrict__ edge,
                             int nnz) {
    int i = blockIdx.x * blockDim.x + threadIdx.x;
    int stride = gridDim.x * blockDim.x;
    for (; i < nnz; i += stride) {
        int k = keys[i];
        int p = atomicAdd(&pos[k], 1);
        edge[p] = make_int2(other[i], __float_as_int(vals[i]));
    }
}

// ---------------- FC + LeakyReLU ---------------------------------------------
__global__ void fc_leaky_kernel(const float* __restrict__ emb,
                                const float* __restrict__ W,   // [D_H, D_IN]
                                const float* __restrict__ b,
                                float* __restrict__ out1,
                                float* __restrict__ out2,
                                int nrows) {
    __shared__ float sWt[D_IN * D_H];  // sWt[k*128 + j] = W[j*64 + k]
    __shared__ float sX[4][D_IN];
    const int j = threadIdx.x;
    for (int idx = j; idx < D_IN * D_H; idx += D_H) {
        int k = idx >> 7, jj = idx & 127;
        sWt[idx] = W[jj * D_IN + k];
    }
    const float bj = b[j];
    __syncthreads();

    for (int rbase = blockIdx.x * 4; rbase < nrows; rbase += gridDim.x * 4) {
        for (int t = j; t < 4 * D_IN; t += D_H) {
            int rr = t >> 6, kk = t & 63;
            int row = rbase + rr;
            sX[rr][kk] = (row < nrows) ? emb[(size_t)row * D_IN + kk] : 0.f;
        }
        __syncthreads();
        float a0 = bj, a1 = bj, a2 = bj, a3 = bj;
        #pragma unroll 8
        for (int k = 0; k < D_IN; k++) {
            float w = sWt[k * D_H + j];
            a0 += w * sX[0][k];
            a1 += w * sX[1][k];
            a2 += w * sX[2][k];
            a3 += w * sX[3][k];
        }
        a0 = leakyf(a0); a1 = leakyf(a1); a2 = leakyf(a2); a3 = leakyf(a3);
        if (rbase + 0 < nrows) { out1[(size_t)(rbase+0)*D_H + j] = a0; out2[(size_t)(rbase+0)*D_H + j] = a0; }
        if (rbase + 1 < nrows) { out1[(size_t)(rbase+1)*D_H + j] = a1; out2[(size_t)(rbase+1)*D_H + j] = a1; }
        if (rbase + 2 < nrows) { out1[(size_t)(rbase+2)*D_H + j] = a2; out2[(size_t)(rbase+2)*D_H + j] = a2; }
        if (rbase + 3 < nrows) { out1[(size_t)(rbase+3)*D_H + j] = a3; out2[(size_t)(rbase+3)*D_H + j] = a3; }
        __syncthreads();
    }
}

// ---------------- CSR gather SpMM: y[r,:] = sum_e val * x[col[e],:] ----------
// One warp per output row; lane owns one float4 (16B) of the 512B feature row.
__global__ void spmm_csr_kernel(const int*  __restrict__ rowptr,
                                const int2* __restrict__ edge,
                                const float* __restrict__ x,
                                float*       __restrict__ y,
                                int nrows) {
    const int lane = threadIdx.x & 31;
    const int row  = (blockIdx.x * blockDim.x + threadIdx.x) >> 5;
    if (row >= nrows) return;
    const int beg = rowptr[row];
    const int end = rowptr[row + 1];
    const float4* __restrict__ x4 = reinterpret_cast<const float4*>(x);
    float ax = 0.f, ay = 0.f, az = 0.f, aw = 0.f;
    for (int base = beg; base < end; base += 32) {
        int e = base + lane;
        int c = 0; float v = 0.f;
        if (e < end) {
            int2 ed = __ldg(edge + e);
            c = ed.x;
            v = __int_as_float(ed.y);
        }
        int m = end - base; if (m > 32) m = 32;
        for (int jj = 0; jj < m; jj++) {
            int   cj = __shfl_sync(0xffffffffu, c, jj);
            float vj = __shfl_sync(0xffffffffu, v, jj);
            float4 xv = __ldg(x4 + (size_t)cj * 32 + lane);
            ax += vj * xv.x;
            ay += vj * xv.y;
            az += vj * xv.z;
            aw += vj * xv.w;
        }
    }
    float4 o; o.x = ax; o.y = ay; o.z = az; o.w = aw;
    reinterpret_cast<float4*>(y)[(size_t)row * 32 + lane] = o;
}

// ---------------- GEMM (X @ W^T) + LayerNorm ---------------------------------
__global__ void gemm_ln_kernel(const float* __restrict__ X,   // [nrows, 128]
                               const float* __restrict__ W,   // [128, 128]
                               const float* __restrict__ g,
                               const float* __restrict__ b,
                               float* __restrict__ out,
                               int nrows) {
    extern __shared__ float sWt[];     // sWt[k*128+j] = W[j*128+k]
    __shared__ float sX[4][D_H];
    __shared__ float sSum[4][4];
    __shared__ float sSq[4][4];
    const int j = threadIdx.x;
    const int w = j >> 5, lane = j & 31;

    for (int idx = j; idx < D_H * D_H; idx += D_H)
        sWt[idx] = W[(idx & 127) * D_H + (idx >> 7)];
    const float gj = g[j];
    const float bj = b[j];
    __syncthreads();

    for (int rbase = blockIdx.x * 4; rbase < nrows; rbase += gridDim.x * 4) {
        #pragma unroll
        for (int t = 0; t < 4; t++) {
            int row = rbase + t;
            sX[t][j] = (row < nrows) ? X[(size_t)row * D_H + j] : 0.f;
        }
        __syncthreads();
        float a0 = 0.f, a1 = 0.f, a2 = 0.f, a3 = 0.f;
        #pragma unroll 8
        for (int k = 0; k < D_H; k++) {
            float ww = sWt[k * D_H + j];
            a0 += ww * sX[0][k];
            a1 += ww * sX[1][k];
            a2 += ww * sX[2][k];
            a3 += ww * sX[3][k];
        }
        float s0 = a0, s1 = a1, s2 = a2, s3 = a3;
        float q0 = a0*a0, q1 = a1*a1, q2 = a2*a2, q3 = a3*a3;
        #pragma unroll
        for (int off = 16; off; off >>= 1) {
            s0 += __shfl_xor_sync(0xffffffffu, s0, off);
            s1 += __shfl_xor_sync(0xffffffffu, s1, off);
            s2 += __shfl_xor_sync(0xffffffffu, s2, off);
            s3 += __shfl_xor_sync(0xffffffffu, s3, off);
            q0 += __shfl_xor_sync(0xffffffffu, q0, off);
            q1 += __shfl_xor_sync(0xffffffffu, q1, off);
            q2 += __shfl_xor_sync(0xffffffffu, q2, off);
            q3 += __shfl_xor_sync(0xffffffffu, q3, off);
        }
        if (lane == 0) {
            sSum[0][w] = s0; sSum[1][w] = s1; sSum[2][w] = s2; sSum[3][w] = s3;
            sSq [0][w] = q0; sSq [1][w] = q1; sSq [2][w] = q2; sSq [3][w] = q3;
        }
        __syncthreads();
        const float inv = 1.f / (float)D_H;
        float mu0 = (sSum[0][0]+sSum[0][1]+sSum[0][2]+sSum[0][3]) * inv;
        float mu1 = (sSum[1][0]+sSum[1][1]+sSum[1][2]+sSum[1][3]) * inv;
        float mu2 = (sSum[2][0]+sSum[2][1]+sSum[2][2]+sSum[2][3]) * inv;
        float mu3 = (sSum[3][0]+sSum[3][1]+sSum[3][2]+sSum[3][3]) * inv;
        float rs0 = rsqrtf((sSq[0][0]+sSq[0][1]+sSq[0][2]+sSq[0][3]) * inv - mu0*mu0 + EPS_F);
        float rs1 = rsqrtf((sSq[1][0]+sSq[1][1]+sSq[1][2]+sSq[1][3]) * inv - mu1*mu1 + EPS_F);
        float rs2 = rsqrtf((sSq[2][0]+sSq[2][1]+sSq[2][2]+sSq[2][3]) * inv - mu2*mu2 + EPS_F);
        float rs3 = rsqrtf((sSq[3][0]+sSq[3][1]+sSq[3][2]+sSq[3][3]) * inv - mu3*mu3 + EPS_F);
        if (rbase + 0 < nrows) out[(size_t)(rbase+0)*D_H + j] = (a0 - mu0) * rs0 * gj + bj;
        if (rbase + 1 < nrows) out[(size_t)(rbase+1)*D_H + j] = (a1 - mu1) * rs1 * gj + bj;
        if (rbase + 2 < nrows) out[(size_t)(rbase+2)*D_H + j] = (a2 - mu2) * rs2 * gj + bj;
        if (rbase + 3 < nrows) out[(size_t)(rbase+3)*D_H + j] = (a3 - mu3) * rs3 * gj + bj;
        __syncthreads();
    }
}

// ---------------- LN + leaky + residual/accumulator update -------------------
// h = leaky(LN(y)*g+b);  feat += h;  acc = (acc + h) * oscale.
__global__ void ln_leaky_update_kernel(const float* __restrict__ y,
                                       const float* __restrict__ g,
                                       const float* __restrict__ b,
                                       float* __restrict__ feat,
                                       float* __restrict__ acc,
                                       int nrows, float oscale) {
    const int lane = threadIdx.x & 31;
    int row  = (blockIdx.x * blockDim.x + threadIdx.x) >> 5;
    int nw   = (gridDim.x * blockDim.x) >> 5;
    const float4 gv = *(reinterpret_cast<const float4*>(g) + lane);
    const float4 bv = *(reinterpret_cast<const float4*>(b) + lane);
    for (; row < nrows; row += nw) {
        float4 v = __ldg(reinterpret_cast<const float4*>(y + (size_t)row * D_H) + lane);
        float s = v.x + v.y + v.z + v.w;
        float q = v.x*v.x + v.y*v.y + v.z*v.z + v.w*v.w;
        #pragma unroll
        for (int off = 16; off; off >>= 1) {
            s += __shfl_xor_sync(0xffffffffu, s, off);
            q += __shfl_xor_sync(0xffffffffu, q, off);
        }
        const float inv = 1.f / (float)D_H;
        float mu = s * inv;
        float rs = rsqrtf(q * inv - mu * mu + EPS_F);
        float4 h;
        h.x = leakyf((v.x - mu) * rs * gv.x + bv.x);
        h.y = leakyf((v.y - mu) * rs * gv.y + bv.y);
        h.z = leakyf((v.z - mu) * rs * gv.z + bv.z);
        h.w = leakyf((v.w - mu) * rs * gv.w + bv.w);
        float4* fp = reinterpret_cast<float4*>(feat + (size_t)row * D_H) + lane;
        float4 fv = *fp;
        fv.x += h.x; fv.y += h.y; fv.z += h.z; fv.w += h.w;
        *fp = fv;
        float4* ap = reinterpret_cast<float4*>(acc + (size_t)row * D_H) + lane;
        float4 av = *ap;
        av.x = (av.x + h.x) * oscale;
        av.y = (av.y + h.y) * oscale;
        av.z = (av.z + h.z) * oscale;
        av.w = (av.w + h.w) * oscale;
        *ap = av;
    }
}

// ---------------- launch ------------------------------------------------------
extern "C" void kernel_launch(void* const* d_in, const int* in_sizes, int n_in,
                              void* d_out, int out_size) {
    const float* emb     = (const float*)d_in[0];
    const float* fc_u_w  = (const float*)d_in[1];
    const float* fc_u_b  = (const float*)d_in[2];
    const float* fc_i_w  = (const float*)d_in[3];
    const float* fc_i_b  = (const float*)d_in[4];
    const float* vals    = (const float*)d_in[5];
    const float* Wu      = (const float*)d_in[6];
    const float* ln1g_u  = (const float*)d_in[7];
    const float* ln1b_u  = (const float*)d_in[8];
    const float* ln2g_u  = (const float*)d_in[9];
    const float* ln2b_u  = (const float*)d_in[10];
    const float* Wi      = (const float*)d_in[11];
    const float* ln1g_i  = (const float*)d_in[12];
    const float* ln1b_i  = (const float*)d_in[13];
    const float* ln2g_i  = (const float*)d_in[14];
    const float* ln2b_i  = (const float*)d_in[15];
    const int*   rows    = (const int*)d_in[16];
    const int*   cols    = (const int*)d_in[17];
    float* out = (float*)d_out;
    const int nnz = in_sizes[5];
    (void)n_in; (void)out_size;

    float *pu, *pi, *tA, *tB;
    int *ptrU, *ptrI, *posU, *posI, *cntU, *cntI;
    int2 *edgeU, *edgeI;
    cudaGetSymbolAddress((void**)&pu, g_u);
    cudaGetSymbolAddress((void**)&pi, g_i);
    cudaGetSymbolAddress((void**)&tA, g_tA);
    cudaGetSymbolAddress((void**)&tB, g_tB);
    cudaGetSymbolAddress((void**)&ptrU, g_ptrU);
    cudaGetSymbolAddress((void**)&ptrI, g_ptrI);
    cudaGetSymbolAddress((void**)&posU, g_posU);
    cudaGetSymbolAddress((void**)&posI, g_posI);
    cudaGetSymbolAddress((void**)&cntU, g_cntU);
    cudaGetSymbolAddress((void**)&cntI, g_cntI);
    cudaGetSymbolAddress((void**)&edgeU, g_edgeU);
    cudaGetSymbolAddress((void**)&edgeI, g_edgeI);

    cudaFuncSetAttribute(gemm_ln_kernel,
                         cudaFuncAttributeMaxDynamicSharedMemorySize,
                         D_H * D_H * (int)sizeof(float));

    const int GL_BLOCKS = 1480;
    const int EB = (nnz + 255) / 256;
    const size_t GLN = D_H * D_H * sizeof(float);

    // -------- CSR build (both directions) --------
    zero_int2arr<<<256, 256>>>(cntU, N_U, cntI, N_I);
    hist_kernel<<<EB, 256>>>(rows, cntU, cols, cntI, nnz);
    scan_kernel<<<1, 1024>>>(cntU, ptrU, posU, N_U);
    scan_kernel<<<1, 1024>>>(cntI, ptrI, posI, N_I);
    build_kernel<<<EB, 256>>>(rows, cols, vals, posU, edgeU, nnz);
    build_kernel<<<EB, 256>>>(cols, rows, vals, posI, edgeI, nnz);

    // -------- initial projections (also init acc = d_out) --------
    fc_leaky_kernel<<<GL_BLOCKS, D_H>>>(emb, fc_u_w, fc_u_b, pu, out, N_U);
    fc_leaky_kernel<<<GL_BLOCKS, D_H>>>(emb + (size_t)N_U * D_IN, fc_i_w, fc_i_b,
                                        pi, out + (size_t)N_U * D_H, N_I);

    const int SPU = (N_U + 7) / 8;   // 8 warps (256 thr) per block, warp-per-row
    const int SPI = (N_I + 7) / 8;

    for (int k = 0; k < N_LAYERS; k++) {
        const float* Wu_k = Wu + (size_t)k * D_H * D_H;
        const float* Wi_k = Wi + (size_t)k * D_H * D_H;
        const float oscale = (k == N_LAYERS - 1) ? (1.f / 3.f) : 1.f;

        // ---- hu: y1 = A^T u (dst=item); lat1 = LN(y1 Wu^T); y2 = A lat1 (dst=user)
        spmm_csr_kernel<<<SPI, 256>>>(ptrI, edgeI, pu, tA, N_I);
        gemm_ln_kernel<<<GL_BLOCKS, D_H, GLN>>>(tA, Wu_k,
                                                ln1g_u + k * D_H, ln1b_u + k * D_H,
                                                tB, N_I);
        spmm_csr_kernel<<<SPU, 256>>>(ptrU, edgeU, tB, tA, N_U);
        ln_leaky_update_kernel<<<(N_U + 7) / 8, 256>>>(tA,
                                                       ln2g_u + k * D_H, ln2b_u + k * D_H,
                                                       pu, out, N_U, oscale);
        // ---- hi: y1 = A i (dst=user); lat1 = LN(y1 Wi^T); y2 = A^T lat1 (dst=item)
        spmm_csr_kernel<<<SPU, 256>>>(ptrU, edgeU, pi, tA, N_U);
        gemm_ln_kernel<<<GL_BLOCKS, D_H, GLN>>>(tA, Wi_k,
                                                ln1g_i + k * D_H, ln1b_i + k * D_H,
                                                tB, N_U);
        spmm_csr_kernel<<<SPI, 256>>>(ptrI, edgeI, tB, tA, N_I);
        ln_leaky_update_kernel<<<(N_I + 7) / 8, 256>>>(tA,
                                                       ln2g_i + k * D_H, ln2b_i + k * D_H,
                                                       pi, out + (size_t)N_U * D_H, N_I, oscale);
    }
}

// round 3
// speedup vs baseline: 1.6878x; 1.0667x over previous
#include <cuda_runtime.h>
#include <cstdint>

#define D_H      128
#define D_IN     64
#define N_U      100000
#define N_I      50000
#define NNZ_MAX  5000000
#define N_LAYERS 2
#define SLOPE_F  0.2f
#define EPS_F    1e-5f
#define CHUNK    1024

// ---------------- scratch (static device globals; no runtime allocation) ----
__device__ __align__(256) float g_u [(size_t)N_U * D_H];
__device__ __align__(256) float g_i [(size_t)N_I * D_H];
__device__ __align__(256) float g_tA[(size_t)N_U * D_H];
__device__ __align__(256) float g_tB[(size_t)N_U * D_H];

// CSR structures (two directions)
__device__ __align__(256) int2 g_edgeU[NNZ_MAX];
__device__ __align__(256) int2 g_edgeI[NNZ_MAX];
__device__ int g_ptrU[N_U + 1];
__device__ int g_ptrI[N_I + 1];
__device__ int g_posU[N_U];
__device__ int g_posI[N_I];
__device__ int g_cntU[N_U];
__device__ int g_cntI[N_I];
__device__ int g_chunkU[(N_U + CHUNK - 1) / CHUNK];
__device__ int g_chunkI[(N_I + CHUNK - 1) / CHUNK];

__device__ __forceinline__ float leakyf(float x) { return x > 0.f ? x : SLOPE_F * x; }

// ---------------- CSR build kernels ------------------------------------------
__global__ void zero_int2arr(int* __restrict__ a, int na, int* __restrict__ b, int nb) {
    int i = blockIdx.x * blockDim.x + threadIdx.x;
    int stride = gridDim.x * blockDim.x;
    for (; i < na; i += stride) a[i] = 0;
    for (i = blockIdx.x * blockDim.x + threadIdx.x; i < nb; i += stride) b[i] = 0;
}

__global__ void hist_kernel(const int* __restrict__ keysA, int* __restrict__ cntA,
                            const int* __restrict__ keysB, int* __restrict__ cntB,
                            int nnz) {
    int i = blockIdx.x * blockDim.x + threadIdx.x;
    int stride = gridDim.x * blockDim.x;
    for (; i < nnz; i += stride) {
        atomicAdd(&cntA[keysA[i]], 1);
        atomicAdd(&cntB[keysB[i]], 1);
    }
}

// scan phase 1: per-chunk sums (one block per CHUNK elements)
__global__ void scan_reduce(const int* __restrict__ cnt, int* __restrict__ chunkSum, int n) {
    __shared__ int sw[8];
    const int tid = threadIdx.x;                 // 256 threads
    const int base = blockIdx.x * CHUNK;
    int s = 0;
    #pragma unroll
    for (int t = 0; t < CHUNK / 256; t++) {
        int idx = base + t * 256 + tid;
        if (idx < n) s += cnt[idx];
    }
    #pragma unroll
    for (int off = 16; off; off >>= 1) s += __shfl_xor_sync(0xffffffffu, s, off);
    if ((tid & 31) == 0) sw[tid >> 5] = s;
    __syncthreads();
    if (tid == 0) {
        int tot = 0;
        #pragma unroll
        for (int w = 0; w < 8; w++) tot += sw[w];
        chunkSum[blockIdx.x] = tot;
    }
}

// scan phase 2: exclusive scan over chunk sums for BOTH directions (tiny)
__global__ void scan_offsets(int* __restrict__ cA, int nA, int* __restrict__ cB, int nB) {
    if (threadIdx.x == 0) {
        int acc = 0;
        for (int c = 0; c < nA; c++) { int v = cA[c]; cA[c] = acc; acc += v; }
    } else if (threadIdx.x == 32) {
        int acc = 0;
        for (int c = 0; c < nB; c++) { int v = cB[c]; cB[c] = acc; acc += v; }
    }
}

// scan phase 3: per-chunk inclusive scan + chunk offset; write ptr and pos
__global__ void scan_write(const int* __restrict__ cnt, const int* __restrict__ chunkOff,
                           int* __restrict__ ptr, int* __restrict__ pos, int n) {
    __shared__ int sdata[CHUNK];
    const int tid = threadIdx.x;                 // CHUNK threads
    const int i = blockIdx.x * CHUNK + tid;
    int v = (i < n) ? cnt[i] : 0;
    sdata[tid] = v;
    __syncthreads();
    #pragma unroll
    for (int off = 1; off < CHUNK; off <<= 1) {
        int t = (tid >= off) ? sdata[tid - off] : 0;
        __syncthreads();
        sdata[tid] += t;
        __syncthreads();
    }
    if (i < n) {
        int off = chunkOff[blockIdx.x];
        int incl = off + sdata[tid];
        ptr[i + 1] = incl;
        pos[i] = incl - v;
    }
    if (i == 0) ptr[0] = 0;
}

// fused build: one pass over edges fills both CSR directions
__global__ void build_both_kernel(const int* __restrict__ rows,
                                  const int* __restrict__ cols,
                                  const float* __restrict__ vals,
                                  int* __restrict__ posU, int* __restrict__ posI,
                                  int2* __restrict__ edgeU, int2* __restrict__ edgeI,
                                  int nnz) {
    int i = blockIdx.x * blockDim.x + threadIdx.x;
    int stride = gridDim.x * blockDim.x;
    for (; i < nnz; i += stride) {
        int r = rows[i];
        int c = cols[i];
        int v = __float_as_int(vals[i]);
        int pu_ = atomicAdd(&posU[r], 1);
        edgeU[pu_] = make_int2(c, v);
        int pi_ = atomicAdd(&posI[c], 1);
        edgeI[pi_] = make_int2(r, v);
    }
}

// ---------------- FC + LeakyReLU ---------------------------------------------
__global__ void fc_leaky_kernel(const float* __restrict__ emb,
                                const float* __restrict__ W,   // [D_H, D_IN]
                                const float* __restrict__ b,
                                float* __restrict__ out1,
                                float* __restrict__ out2,
                                int nrows) {
    __shared__ float sWt[D_IN * D_H];
    __shared__ float sX[4][D_IN];
    const int j = threadIdx.x;
    for (int idx = j; idx < D_IN * D_H; idx += D_H) {
        int k = idx >> 7, jj = idx & 127;
        sWt[idx] = W[jj * D_IN + k];
    }
    const float bj = b[j];
    __syncthreads();

    for (int rbase = blockIdx.x * 4; rbase < nrows; rbase += gridDim.x * 4) {
        for (int t = j; t < 4 * D_IN; t += D_H) {
            int rr = t >> 6, kk = t & 63;
            int row = rbase + rr;
            sX[rr][kk] = (row < nrows) ? emb[(size_t)row * D_IN + kk] : 0.f;
        }
        __syncthreads();
        float a0 = bj, a1 = bj, a2 = bj, a3 = bj;
        #pragma unroll 8
        for (int k = 0; k < D_IN; k++) {
            float w = sWt[k * D_H + j];
            a0 += w * sX[0][k];
            a1 += w * sX[1][k];
            a2 += w * sX[2][k];
            a3 += w * sX[3][k];
        }
        a0 = leakyf(a0); a1 = leakyf(a1); a2 = leakyf(a2); a3 = leakyf(a3);
        if (rbase + 0 < nrows) { out1[(size_t)(rbase+0)*D_H + j] = a0; out2[(size_t)(rbase+0)*D_H + j] = a0; }
        if (rbase + 1 < nrows) { out1[(size_t)(rbase+1)*D_H + j] = a1; out2[(size_t)(rbase+1)*D_H + j] = a1; }
        if (rbase + 2 < nrows) { out1[(size_t)(rbase+2)*D_H + j] = a2; out2[(size_t)(rbase+2)*D_H + j] = a2; }
        if (rbase + 3 < nrows) { out1[(size_t)(rbase+3)*D_H + j] = a3; out2[(size_t)(rbase+3)*D_H + j] = a3; }
        __syncthreads();
    }
}

// ---------------- CSR gather SpMM --------------------------------------------
__global__ void spmm_csr_kernel(const int*  __restrict__ rowptr,
                                const int2* __restrict__ edge,
                                const float* __restrict__ x,
                                float*       __restrict__ y,
                                int nrows) {
    const int lane = threadIdx.x & 31;
    const int row  = (blockIdx.x * blockDim.x + threadIdx.x) >> 5;
    if (row >= nrows) return;
    const int beg = rowptr[row];
    const int end = rowptr[row + 1];
    const float4* __restrict__ x4 = reinterpret_cast<const float4*>(x);
    float ax = 0.f, ay = 0.f, az = 0.f, aw = 0.f;
    for (int base = beg; base < end; base += 32) {
        int e = base + lane;
        int c = 0; float v = 0.f;
        if (e < end) {
            int2 ed = __ldg(edge + e);
            c = ed.x;
            v = __int_as_float(ed.y);
        }
        int m = end - base; if (m > 32) m = 32;
        for (int jj = 0; jj < m; jj++) {
            int   cj = __shfl_sync(0xffffffffu, c, jj);
            float vj = __shfl_sync(0xffffffffu, v, jj);
            float4 xv = __ldg(x4 + (size_t)cj * 32 + lane);
            ax += vj * xv.x;
            ay += vj * xv.y;
            az += vj * xv.z;
            aw += vj * xv.w;
        }
    }
    float4 o; o.x = ax; o.y = ay; o.z = az; o.w = aw;
    reinterpret_cast<float4*>(y)[(size_t)row * 32 + lane] = o;
}

// ---------------- GEMM (X @ W^T) + LayerNorm ---------------------------------
__global__ void gemm_ln_kernel(const float* __restrict__ X,
                               const float* __restrict__ W,
                               const float* __restrict__ g,
                               const float* __restrict__ b,
                               float* __restrict__ out,
                               int nrows) {
    extern __shared__ float sWt[];
    __shared__ float sX[4][D_H];
    __shared__ float sSum[4][4];
    __shared__ float sSq[4][4];
    const int j = threadIdx.x;
    const int w = j >> 5, lane = j & 31;

    for (int idx = j; idx < D_H * D_H; idx += D_H)
        sWt[idx] = W[(idx & 127) * D_H + (idx >> 7)];
    const float gj = g[j];
    const float bj = b[j];
    __syncthreads();

    for (int rbase = blockIdx.x * 4; rbase < nrows; rbase += gridDim.x * 4) {
        #pragma unroll
        for (int t = 0; t < 4; t++) {
            int row = rbase + t;
            sX[t][j] = (row < nrows) ? X[(size_t)row * D_H + j] : 0.f;
        }
        __syncthreads();
        float a0 = 0.f, a1 = 0.f, a2 = 0.f, a3 = 0.f;
        #pragma unroll 8
        for (int k = 0; k < D_H; k++) {
            float ww = sWt[k * D_H + j];
            a0 += ww * sX[0][k];
            a1 += ww * sX[1][k];
            a2 += ww * sX[2][k];
            a3 += ww * sX[3][k];
        }
        float s0 = a0, s1 = a1, s2 = a2, s3 = a3;
        float q0 = a0*a0, q1 = a1*a1, q2 = a2*a2, q3 = a3*a3;
        #pragma unroll
        for (int off = 16; off; off >>= 1) {
            s0 += __shfl_xor_sync(0xffffffffu, s0, off);
            s1 += __shfl_xor_sync(0xffffffffu, s1, off);
            s2 += __shfl_xor_sync(0xffffffffu, s2, off);
            s3 += __shfl_xor_sync(0xffffffffu, s3, off);
            q0 += __shfl_xor_sync(0xffffffffu, q0, off);
            q1 += __shfl_xor_sync(0xffffffffu, q1, off);
            q2 += __shfl_xor_sync(0xffffffffu, q2, off);
            q3 += __shfl_xor_sync(0xffffffffu, q3, off);
        }
        if (lane == 0) {
            sSum[0][w] = s0; sSum[1][w] = s1; sSum[2][w] = s2; sSum[3][w] = s3;
            sSq [0][w] = q0; sSq [1][w] = q1; sSq [2][w] = q2; sSq [3][w] = q3;
        }
        __syncthreads();
        const float inv = 1.f / (float)D_H;
        float mu0 = (sSum[0][0]+sSum[0][1]+sSum[0][2]+sSum[0][3]) * inv;
        float mu1 = (sSum[1][0]+sSum[1][1]+sSum[1][2]+sSum[1][3]) * inv;
        float mu2 = (sSum[2][0]+sSum[2][1]+sSum[2][2]+sSum[2][3]) * inv;
        float mu3 = (sSum[3][0]+sSum[3][1]+sSum[3][2]+sSum[3][3]) * inv;
        float rs0 = rsqrtf((sSq[0][0]+sSq[0][1]+sSq[0][2]+sSq[0][3]) * inv - mu0*mu0 + EPS_F);
        float rs1 = rsqrtf((sSq[1][0]+sSq[1][1]+sSq[1][2]+sSq[1][3]) * inv - mu1*mu1 + EPS_F);
        float rs2 = rsqrtf((sSq[2][0]+sSq[2][1]+sSq[2][2]+sSq[2][3]) * inv - mu2*mu2 + EPS_F);
        float rs3 = rsqrtf((sSq[3][0]+sSq[3][1]+sSq[3][2]+sSq[3][3]) * inv - mu3*mu3 + EPS_F);
        if (rbase + 0 < nrows) out[(size_t)(rbase+0)*D_H + j] = (a0 - mu0) * rs0 * gj + bj;
        if (rbase + 1 < nrows) out[(size_t)(rbase+1)*D_H + j] = (a1 - mu1) * rs1 * gj + bj;
        if (rbase + 2 < nrows) out[(size_t)(rbase+2)*D_H + j] = (a2 - mu2) * rs2 * gj + bj;
        if (rbase + 3 < nrows) out[(size_t)(rbase+3)*D_H + j] = (a3 - mu3) * rs3 * gj + bj;
        __syncthreads();
    }
}

// ---------------- LN + leaky + residual/accumulator update -------------------
__global__ void ln_leaky_update_kernel(const float* __restrict__ y,
                                       const float* __restrict__ g,
                                       const float* __restrict__ b,
                                       float* __restrict__ feat,
                                       float* __restrict__ acc,
                                       int nrows, float oscale) {
    const int lane = threadIdx.x & 31;
    int row  = (blockIdx.x * blockDim.x + threadIdx.x) >> 5;
    int nw   = (gridDim.x * blockDim.x) >> 5;
    const float4 gv = *(reinterpret_cast<const float4*>(g) + lane);
    const float4 bv = *(reinterpret_cast<const float4*>(b) + lane);
    for (; row < nrows; row += nw) {
        float4 v = __ldg(reinterpret_cast<const float4*>(y + (size_t)row * D_H) + lane);
        float s = v.x + v.y + v.z + v.w;
        float q = v.x*v.x + v.y*v.y + v.z*v.z + v.w*v.w;
        #pragma unroll
        for (int off = 16; off; off >>= 1) {
            s += __shfl_xor_sync(0xffffffffu, s, off);
            q += __shfl_xor_sync(0xffffffffu, q, off);
        }
        const float inv = 1.f / (float)D_H;
        float mu = s * inv;
        float rs = rsqrtf(q * inv - mu * mu + EPS_F);
        float4 h;
        h.x = leakyf((v.x - mu) * rs * gv.x + bv.x);
        h.y = leakyf((v.y - mu) * rs * gv.y + bv.y);
        h.z = leakyf((v.z - mu) * rs * gv.z + bv.z);
        h.w = leakyf((v.w - mu) * rs * gv.w + bv.w);
        float4* fp = reinterpret_cast<float4*>(feat + (size_t)row * D_H) + lane;
        float4 fv = *fp;
        fv.x += h.x; fv.y += h.y; fv.z += h.z; fv.w += h.w;
        *fp = fv;
        float4* ap = reinterpret_cast<float4*>(acc + (size_t)row * D_H) + lane;
        float4 av = *ap;
        av.x = (av.x + h.x) * oscale;
        av.y = (av.y + h.y) * oscale;
        av.z = (av.z + h.z) * oscale;
        av.w = (av.w + h.w) * oscale;
        *ap = av;
    }
}

// ---------------- launch ------------------------------------------------------
extern "C" void kernel_launch(void* const* d_in, const int* in_sizes, int n_in,
                              void* d_out, int out_size) {
    const float* emb     = (const float*)d_in[0];
    const float* fc_u_w  = (const float*)d_in[1];
    const float* fc_u_b  = (const float*)d_in[2];
    const float* fc_i_w  = (const float*)d_in[3];
    const float* fc_i_b  = (const float*)d_in[4];
    const float* vals    = (const float*)d_in[5];
    const float* Wu      = (const float*)d_in[6];
    const float* ln1g_u  = (const float*)d_in[7];
    const float* ln1b_u  = (const float*)d_in[8];
    const float* ln2g_u  = (const float*)d_in[9];
    const float* ln2b_u  = (const float*)d_in[10];
    const float* Wi      = (const float*)d_in[11];
    const float* ln1g_i  = (const float*)d_in[12];
    const float* ln1b_i  = (const float*)d_in[13];
    const float* ln2g_i  = (const float*)d_in[14];
    const float* ln2b_i  = (const float*)d_in[15];
    const int*   rows    = (const int*)d_in[16];
    const int*   cols    = (const int*)d_in[17];
    float* out = (float*)d_out;
    const int nnz = in_sizes[5];
    (void)n_in; (void)out_size;

    float *pu, *pi, *tA, *tB;
    int *ptrU, *ptrI, *posU, *posI, *cntU, *cntI, *chU, *chI;
    int2 *edgeU, *edgeI;
    cudaGetSymbolAddress((void**)&pu, g_u);
    cudaGetSymbolAddress((void**)&pi, g_i);
    cudaGetSymbolAddress((void**)&tA, g_tA);
    cudaGetSymbolAddress((void**)&tB, g_tB);
    cudaGetSymbolAddress((void**)&ptrU, g_ptrU);
    cudaGetSymbolAddress((void**)&ptrI, g_ptrI);
    cudaGetSymbolAddress((void**)&posU, g_posU);
    cudaGetSymbolAddress((void**)&posI, g_posI);
    cudaGetSymbolAddress((void**)&cntU, g_cntU);
    cudaGetSymbolAddress((void**)&cntI, g_cntI);
    cudaGetSymbolAddress((void**)&chU, g_chunkU);
    cudaGetSymbolAddress((void**)&chI, g_chunkI);
    cudaGetSymbolAddress((void**)&edgeU, g_edgeU);
    cudaGetSymbolAddress((void**)&edgeI, g_edgeI);

    cudaFuncSetAttribute(gemm_ln_kernel,
                         cudaFuncAttributeMaxDynamicSharedMemorySize,
                         D_H * D_H * (int)sizeof(float));

    const int GL_BLOCKS = 1480;
    const int EB = (nnz + 255) / 256;
    const size_t GLN = D_H * D_H * sizeof(float);
    const int NCHU = (N_U + CHUNK - 1) / CHUNK;   // 98
    const int NCHI = (N_I + CHUNK - 1) / CHUNK;   // 49

    // -------- CSR build (both directions) --------
    zero_int2arr<<<256, 256>>>(cntU, N_U, cntI, N_I);
    hist_kernel<<<EB, 256>>>(rows, cntU, cols, cntI, nnz);
    scan_reduce<<<NCHU, 256>>>(cntU, chU, N_U);
    scan_reduce<<<NCHI, 256>>>(cntI, chI, N_I);
    scan_offsets<<<1, 64>>>(chU, NCHU, chI, NCHI);
    scan_write<<<NCHU, CHUNK>>>(cntU, chU, ptrU, posU, N_U);
    scan_write<<<NCHI, CHUNK>>>(cntI, chI, ptrI, posI, N_I);
    build_both_kernel<<<EB, 256>>>(rows, cols, vals, posU, posI, edgeU, edgeI, nnz);

    // -------- initial projections (also init acc = d_out) --------
    fc_leaky_kernel<<<GL_BLOCKS, D_H>>>(emb, fc_u_w, fc_u_b, pu, out, N_U);
    fc_leaky_kernel<<<GL_BLOCKS, D_H>>>(emb + (size_t)N_U * D_IN, fc_i_w, fc_i_b,
                                        pi, out + (size_t)N_U * D_H, N_I);

    const int SPU = (N_U + 7) / 8;
    const int SPI = (N_I + 7) / 8;

    for (int k = 0; k < N_LAYERS; k++) {
        const float* Wu_k = Wu + (size_t)k * D_H * D_H;
        const float* Wi_k = Wi + (size_t)k * D_H * D_H;
        const float oscale = (k == N_LAYERS - 1) ? (1.f / 3.f) : 1.f;

        spmm_csr_kernel<<<SPI, 256>>>(ptrI, edgeI, pu, tA, N_I);
        gemm_ln_kernel<<<GL_BLOCKS, D_H, GLN>>>(tA, Wu_k,
                                                ln1g_u + k * D_H, ln1b_u + k * D_H,
                                                tB, N_I);
        spmm_csr_kernel<<<SPU, 256>>>(ptrU, edgeU, tB, tA, N_U);
        ln_leaky_update_kernel<<<(N_U + 7) / 8, 256>>>(tA,
                                                       ln2g_u + k * D_H, ln2b_u + k * D_H,
                                                       pu, out, N_U, oscale);

        spmm_csr_kernel<<<SPU, 256>>>(ptrU, edgeU, pi, tA, N_U);
        gemm_ln_kernel<<<GL_BLOCKS, D_H, GLN>>>(tA, Wi_k,
                                                ln1g_i + k * D_H, ln1b_i + k * D_H,
                                                tB, N_U);
        spmm_csr_kernel<<<SPI, 256>>>(ptrI, edgeI, tB, tA, N_I);
        ln_leaky_update_kernel<<<(N_I + 7) / 8, 256>>>(tA,
                                                       ln2g_i + k * D_H, ln2b_i + k * D_H,
                                                       pi, out + (size_t)N_U * D_H, N_I, oscale);
    }
}

// round 4
// speedup vs baseline: 2.1190x; 1.2555x over previous
#include <cuda_runtime.h>
#include <cuda_fp16.h>
#include <cstdint>

#define D_H      128
#define D_IN     64
#define N_U      100000
#define N_I      50000
#define NNZ_MAX  5000000
#define N_LAYERS 2
#define SLOPE_F  0.2f
#define EPS_F    1e-5f
#define CHUNK    1024

// ---------------- scratch (static device globals) ---------------------------
__device__ __align__(256) __half g_hU[(size_t)N_U * D_H];   // user features (fp16)
__device__ __align__(256) __half g_hI[(size_t)N_I * D_H];   // item features (fp16)
__device__ __align__(256) __half g_lU[(size_t)N_U * D_H];   // lat1 (fp16), U-sized
__device__ __align__(256) __half g_lI[(size_t)N_I * D_H];   // lat1 (fp16), I-sized
__device__ __align__(256) float  g_fU[(size_t)N_U * D_H];   // fp32 spmm out, U-sized
__device__ __align__(256) float  g_fI[(size_t)N_I * D_H];   // fp32 spmm out, I-sized

__device__ __align__(256) int2 g_edgeU[NNZ_MAX];
__device__ __align__(256) int2 g_edgeI[NNZ_MAX];
__device__ int g_ptrU[N_U + 1];
__device__ int g_ptrI[N_I + 1];
__device__ int g_posU[N_U];
__device__ int g_posI[N_I];
__device__ int g_cntU[N_U];
__device__ int g_cntI[N_I];
__device__ int g_chunkU[(N_U + CHUNK - 1) / CHUNK];
__device__ int g_chunkI[(N_I + CHUNK - 1) / CHUNK];

__device__ __forceinline__ float leakyf(float x) { return x > 0.f ? x : SLOPE_F * x; }

// ---------------- CSR build ---------------------------------------------------
__global__ void zero_int2arr(int* __restrict__ a, int na, int* __restrict__ b, int nb) {
    int i = blockIdx.x * blockDim.x + threadIdx.x;
    int stride = gridDim.x * blockDim.x;
    for (; i < na; i += stride) a[i] = 0;
    for (i = blockIdx.x * blockDim.x + threadIdx.x; i < nb; i += stride) b[i] = 0;
}

__global__ void hist_kernel(const int* __restrict__ keysA, int* __restrict__ cntA,
                            const int* __restrict__ keysB, int* __restrict__ cntB,
                            int nnz) {
    int i = blockIdx.x * blockDim.x + threadIdx.x;
    int stride = gridDim.x * blockDim.x;
    for (; i < nnz; i += stride) {
        atomicAdd(&cntA[keysA[i]], 1);
        atomicAdd(&cntB[keysB[i]], 1);
    }
}

__global__ void scan_reduce(const int* __restrict__ cnt, int* __restrict__ chunkSum, int n) {
    __shared__ int sw[8];
    const int tid = threadIdx.x;
    const int base = blockIdx.x * CHUNK;
    int s = 0;
    #pragma unroll
    for (int t = 0; t < CHUNK / 256; t++) {
        int idx = base + t * 256 + tid;
        if (idx < n) s += cnt[idx];
    }
    #pragma unroll
    for (int off = 16; off; off >>= 1) s += __shfl_xor_sync(0xffffffffu, s, off);
    if ((tid & 31) == 0) sw[tid >> 5] = s;
    __syncthreads();
    if (tid == 0) {
        int tot = 0;
        #pragma unroll
        for (int w = 0; w < 8; w++) tot += sw[w];
        chunkSum[blockIdx.x] = tot;
    }
}

__global__ void scan_offsets(int* __restrict__ cA, int nA, int* __restrict__ cB, int nB) {
    if (threadIdx.x == 0) {
        int acc = 0;
        for (int c = 0; c < nA; c++) { int v = cA[c]; cA[c] = acc; acc += v; }
    } else if (threadIdx.x == 32) {
        int acc = 0;
        for (int c = 0; c < nB; c++) { int v = cB[c]; cB[c] = acc; acc += v; }
    }
}

__global__ void scan_write(const int* __restrict__ cnt, const int* __restrict__ chunkOff,
                           int* __restrict__ ptr, int* __restrict__ pos, int n) {
    __shared__ int sdata[CHUNK];
    const int tid = threadIdx.x;
    const int i = blockIdx.x * CHUNK + tid;
    int v = (i < n) ? cnt[i] : 0;
    sdata[tid] = v;
    __syncthreads();
    #pragma unroll
    for (int off = 1; off < CHUNK; off <<= 1) {
        int t = (tid >= off) ? sdata[tid - off] : 0;
        __syncthreads();
        sdata[tid] += t;
        __syncthreads();
    }
    if (i < n) {
        int off = chunkOff[blockIdx.x];
        int incl = off + sdata[tid];
        ptr[i + 1] = incl;
        pos[i] = incl - v;
    }
    if (i == 0) ptr[0] = 0;
}

__global__ void build_both_kernel(const int* __restrict__ rows,
                                  const int* __restrict__ cols,
                                  const float* __restrict__ vals,
                                  int* __restrict__ posU, int* __restrict__ posI,
                                  int2* __restrict__ edgeU, int2* __restrict__ edgeI,
                                  int nnz) {
    int i = blockIdx.x * blockDim.x + threadIdx.x;
    int stride = gridDim.x * blockDim.x;
    for (; i < nnz; i += stride) {
        int r = rows[i];
        int c = cols[i];
        int v = __float_as_int(vals[i]);
        int pu_ = atomicAdd(&posU[r], 1);
        edgeU[pu_] = make_int2(c, v);
        int pi_ = atomicAdd(&posI[c], 1);
        edgeI[pi_] = make_int2(r, v);
    }
}

// ---------------- FC + LeakyReLU: half features + fp32 acc init --------------
__global__ void fc_leaky_kernel(const float* __restrict__ emb,
                                const float* __restrict__ W,   // [D_H, D_IN]
                                const float* __restrict__ b,
                                __half* __restrict__ outh,
                                float*  __restrict__ outf,
                                int nrows) {
    __shared__ float sWt[D_IN * D_H];
    __shared__ float sX[4][D_IN];
    const int j = threadIdx.x;
    for (int idx = j; idx < D_IN * D_H; idx += D_H) {
        int k = idx >> 7, jj = idx & 127;
        sWt[idx] = W[jj * D_IN + k];
    }
    const float bj = b[j];
    __syncthreads();

    for (int rbase = blockIdx.x * 4; rbase < nrows; rbase += gridDim.x * 4) {
        for (int t = j; t < 4 * D_IN; t += D_H) {
            int rr = t >> 6, kk = t & 63;
            int row = rbase + rr;
            sX[rr][kk] = (row < nrows) ? emb[(size_t)row * D_IN + kk] : 0.f;
        }
        __syncthreads();
        float a0 = bj, a1 = bj, a2 = bj, a3 = bj;
        #pragma unroll 8
        for (int k = 0; k < D_IN; k++) {
            float w = sWt[k * D_H + j];
            a0 += w * sX[0][k];
            a1 += w * sX[1][k];
            a2 += w * sX[2][k];
            a3 += w * sX[3][k];
        }
        a0 = leakyf(a0); a1 = leakyf(a1); a2 = leakyf(a2); a3 = leakyf(a3);
        if (rbase + 0 < nrows) { outh[(size_t)(rbase+0)*D_H + j] = __float2half(a0); outf[(size_t)(rbase+0)*D_H + j] = a0; }
        if (rbase + 1 < nrows) { outh[(size_t)(rbase+1)*D_H + j] = __float2half(a1); outf[(size_t)(rbase+1)*D_H + j] = a1; }
        if (rbase + 2 < nrows) { outh[(size_t)(rbase+2)*D_H + j] = __float2half(a2); outf[(size_t)(rbase+2)*D_H + j] = a2; }
        if (rbase + 3 < nrows) { outh[(size_t)(rbase+3)*D_H + j] = __float2half(a3); outf[(size_t)(rbase+3)*D_H + j] = a3; }
        __syncthreads();
    }
}

// ---------------- CSR gather SpMM (fp16 gathers, fp32 accumulate) ------------
// warp per row; lane owns features [4*lane .. 4*lane+3] (8B fp16 per lane).
__device__ __forceinline__ void spmm_job(const int*  __restrict__ rowptr,
                                         const int2* __restrict__ edge,
                                         const __half* __restrict__ x,
                                         float* __restrict__ y,
                                         int nrows, int bid) {
    const int lane = threadIdx.x & 31;
    const int row  = bid * 8 + ((int)threadIdx.x >> 5);
    if (row >= nrows) return;
    const int beg = rowptr[row];
    const int end = rowptr[row + 1];
    const uint2* __restrict__ x2 = reinterpret_cast<const uint2*>(x);
    float ax = 0.f, ay = 0.f, az = 0.f, aw = 0.f;
    for (int base = beg; base < end; base += 32) {
        int e = base + lane;
        int c = 0; float v = 0.f;
        if (e < end) {
            int2 ed = __ldg(edge + e);
            c = ed.x;
            v = __int_as_float(ed.y);
        }
        int m = end - base; if (m > 32) m = 32;
        for (int jj = 0; jj < m; jj++) {
            int   cj = __shfl_sync(0xffffffffu, c, jj);
            float vj = __shfl_sync(0xffffffffu, v, jj);
            uint2 d = __ldg(x2 + (size_t)cj * 32 + lane);
            __half2 h0 = *reinterpret_cast<__half2*>(&d.x);
            __half2 h1 = *reinterpret_cast<__half2*>(&d.y);
            float2 f0 = __half22float2(h0);
            float2 f1 = __half22float2(h1);
            ax += vj * f0.x;
            ay += vj * f0.y;
            az += vj * f1.x;
            aw += vj * f1.y;
        }
    }
    float4 o; o.x = ax; o.y = ay; o.z = az; o.w = aw;
    reinterpret_cast<float4*>(y)[(size_t)row * 32 + lane] = o;
}

__global__ void spmm_dual(const int*  __restrict__ ptrA, const int2* __restrict__ edgeA,
                          const __half* __restrict__ xA, float* __restrict__ yA,
                          int nA, int blocksA,
                          const int*  __restrict__ ptrB, const int2* __restrict__ edgeB,
                          const __half* __restrict__ xB, float* __restrict__ yB,
                          int nB) {
    if ((int)blockIdx.x < blocksA)
        spmm_job(ptrA, edgeA, xA, yA, nA, blockIdx.x);
    else
        spmm_job(ptrB, edgeB, xB, yB, nB, blockIdx.x - blocksA);
}

// ---------------- GEMM (X @ W^T) + LayerNorm, half output --------------------
__device__ __forceinline__ void gemm_ln_job(const float* __restrict__ X,
                                            const float* __restrict__ W,
                                            const float* __restrict__ g,
                                            const float* __restrict__ b,
                                            __half* __restrict__ out,
                                            int nrows, int bid, int nblocks,
                                            float* sWt) {
    __shared__ float sX[4][D_H];
    __shared__ float sSum[4][4];
    __shared__ float sSq[4][4];
    const int j = threadIdx.x;
    const int w = j >> 5, lane = j & 31;

    for (int idx = j; idx < D_H * D_H; idx += D_H)
        sWt[idx] = W[(idx & 127) * D_H + (idx >> 7)];
    const float gj = g[j];
    const float bj = b[j];
    __syncthreads();

    for (int rbase = bid * 4; rbase < nrows; rbase += nblocks * 4) {
        #pragma unroll
        for (int t = 0; t < 4; t++) {
            int row = rbase + t;
            sX[t][j] = (row < nrows) ? X[(size_t)row * D_H + j] : 0.f;
        }
        __syncthreads();
        float a0 = 0.f, a1 = 0.f, a2 = 0.f, a3 = 0.f;
        #pragma unroll 8
        for (int k = 0; k < D_H; k++) {
            float ww = sWt[k * D_H + j];
            a0 += ww * sX[0][k];
            a1 += ww * sX[1][k];
            a2 += ww * sX[2][k];
            a3 += ww * sX[3][k];
        }
        float s0 = a0, s1 = a1, s2 = a2, s3 = a3;
        float q0 = a0*a0, q1 = a1*a1, q2 = a2*a2, q3 = a3*a3;
        #pragma unroll
        for (int off = 16; off; off >>= 1) {
            s0 += __shfl_xor_sync(0xffffffffu, s0, off);
            s1 += __shfl_xor_sync(0xffffffffu, s1, off);
            s2 += __shfl_xor_sync(0xffffffffu, s2, off);
            s3 += __shfl_xor_sync(0xffffffffu, s3, off);
            q0 += __shfl_xor_sync(0xffffffffu, q0, off);
            q1 += __shfl_xor_sync(0xffffffffu, q1, off);
            q2 += __shfl_xor_sync(0xffffffffu, q2, off);
            q3 += __shfl_xor_sync(0xffffffffu, q3, off);
        }
        if (lane == 0) {
            sSum[0][w] = s0; sSum[1][w] = s1; sSum[2][w] = s2; sSum[3][w] = s3;
            sSq [0][w] = q0; sSq [1][w] = q1; sSq [2][w] = q2; sSq [3][w] = q3;
        }
        __syncthreads();
        const float inv = 1.f / (float)D_H;
        float mu0 = (sSum[0][0]+sSum[0][1]+sSum[0][2]+sSum[0][3]) * inv;
        float mu1 = (sSum[1][0]+sSum[1][1]+sSum[1][2]+sSum[1][3]) * inv;
        float mu2 = (sSum[2][0]+sSum[2][1]+sSum[2][2]+sSum[2][3]) * inv;
        float mu3 = (sSum[3][0]+sSum[3][1]+sSum[3][2]+sSum[3][3]) * inv;
        float rs0 = rsqrtf((sSq[0][0]+sSq[0][1]+sSq[0][2]+sSq[0][3]) * inv - mu0*mu0 + EPS_F);
        float rs1 = rsqrtf((sSq[1][0]+sSq[1][1]+sSq[1][2]+sSq[1][3]) * inv - mu1*mu1 + EPS_F);
        float rs2 = rsqrtf((sSq[2][0]+sSq[2][1]+sSq[2][2]+sSq[2][3]) * inv - mu2*mu2 + EPS_F);
        float rs3 = rsqrtf((sSq[3][0]+sSq[3][1]+sSq[3][2]+sSq[3][3]) * inv - mu3*mu3 + EPS_F);
        if (rbase + 0 < nrows) out[(size_t)(rbase+0)*D_H + j] = __float2half((a0 - mu0) * rs0 * gj + bj);
        if (rbase + 1 < nrows) out[(size_t)(rbase+1)*D_H + j] = __float2half((a1 - mu1) * rs1 * gj + bj);
        if (rbase + 2 < nrows) out[(size_t)(rbase+2)*D_H + j] = __float2half((a2 - mu2) * rs2 * gj + bj);
        if (rbase + 3 < nrows) out[(size_t)(rbase+3)*D_H + j] = __float2half((a3 - mu3) * rs3 * gj + bj);
        __syncthreads();
    }
}

__global__ void gemm_ln_dual(const float* __restrict__ XA, const float* __restrict__ WA,
                             const float* __restrict__ gA, const float* __restrict__ bA,
                             __half* __restrict__ outA, int nA, int blocksA,
                             const float* __restrict__ XB, const float* __restrict__ WB,
                             const float* __restrict__ gB, const float* __restrict__ bB,
                             __half* __restrict__ outB, int nB, int blocksB) {
    extern __shared__ float sWt[];
    if ((int)blockIdx.x < blocksA)
        gemm_ln_job(XA, WA, gA, bA, outA, nA, blockIdx.x, blocksA, sWt);
    else
        gemm_ln_job(XB, WB, gB, bB, outB, nB, blockIdx.x - blocksA, blocksB, sWt);
}

// ---------------- LN + leaky + residual/accumulator update -------------------
// h = leaky(LN(y)*g+b); feat(half) += h; acc(fp32) = (acc + h) * oscale.
__device__ __forceinline__ void ln_update_job(const float* __restrict__ y,
                                              const float* __restrict__ g,
                                              const float* __restrict__ b,
                                              __half* __restrict__ feat,
                                              float* __restrict__ acc,
                                              int nrows, int bid, float oscale) {
    const int lane = threadIdx.x & 31;
    const int row = bid * 8 + ((int)threadIdx.x >> 5);
    if (row >= nrows) return;
    const float4 gv = *(reinterpret_cast<const float4*>(g) + lane);
    const float4 bv = *(reinterpret_cast<const float4*>(b) + lane);
    float4 v = __ldg(reinterpret_cast<const float4*>(y + (size_t)row * D_H) + lane);
    float s = v.x + v.y + v.z + v.w;
    float q = v.x*v.x + v.y*v.y + v.z*v.z + v.w*v.w;
    #pragma unroll
    for (int off = 16; off; off >>= 1) {
        s += __shfl_xor_sync(0xffffffffu, s, off);
        q += __shfl_xor_sync(0xffffffffu, q, off);
    }
    const float inv = 1.f / (float)D_H;
    float mu = s * inv;
    float rs = rsqrtf(q * inv - mu * mu + EPS_F);
    float4 h;
    h.x = leakyf((v.x - mu) * rs * gv.x + bv.x);
    h.y = leakyf((v.y - mu) * rs * gv.y + bv.y);
    h.z = leakyf((v.z - mu) * rs * gv.z + bv.z);
    h.w = leakyf((v.w - mu) * rs * gv.w + bv.w);
    // feat (half) += h
    uint2* fp = reinterpret_cast<uint2*>(feat) + (size_t)row * 32 + lane;
    uint2 fd = *fp;
    __half2 f0 = *reinterpret_cast<__half2*>(&fd.x);
    __half2 f1 = *reinterpret_cast<__half2*>(&fd.y);
    float2 ff0 = __half22float2(f0);
    float2 ff1 = __half22float2(f1);
    ff0.x += h.x; ff0.y += h.y; ff1.x += h.z; ff1.y += h.w;
    __half2 o0 = __floats2half2_rn(ff0.x, ff0.y);
    __half2 o1 = __floats2half2_rn(ff1.x, ff1.y);
    fd.x = *reinterpret_cast<unsigned int*>(&o0);
    fd.y = *reinterpret_cast<unsigned int*>(&o1);
    *fp = fd;
    // acc (fp32)
    float4* ap = reinterpret_cast<float4*>(acc) + (size_t)row * 32 + lane;
    float4 av = *ap;
    av.x = (av.x + h.x) * oscale;
    av.y = (av.y + h.y) * oscale;
    av.z = (av.z + h.z) * oscale;
    av.w = (av.w + h.w) * oscale;
    *ap = av;
}

__global__ void ln_update_dual(const float* __restrict__ yA,
                               const float* __restrict__ gA, const float* __restrict__ bA,
                               __half* __restrict__ featA, float* __restrict__ accA,
                               int nA, int blocksA,
                               const float* __restrict__ yB,
                               const float* __restrict__ gB, const float* __restrict__ bB,
                               __half* __restrict__ featB, float* __restrict__ accB,
                               int nB, float oscale) {
    if ((int)blockIdx.x < blocksA)
        ln_update_job(yA, gA, bA, featA, accA, nA, blockIdx.x, oscale);
    else
        ln_update_job(yB, gB, bB, featB, accB, nB, blockIdx.x - blocksA, oscale);
}

// ---------------- launch ------------------------------------------------------
extern "C" void kernel_launch(void* const* d_in, const int* in_sizes, int n_in,
                              void* d_out, int out_size) {
    const float* emb     = (const float*)d_in[0];
    const float* fc_u_w  = (const float*)d_in[1];
    const float* fc_u_b  = (const float*)d_in[2];
    const float* fc_i_w  = (const float*)d_in[3];
    const float* fc_i_b  = (const float*)d_in[4];
    const float* vals    = (const float*)d_in[5];
    const float* Wu      = (const float*)d_in[6];
    const float* ln1g_u  = (const float*)d_in[7];
    const float* ln1b_u  = (const float*)d_in[8];
    const float* ln2g_u  = (const float*)d_in[9];
    const float* ln2b_u  = (const float*)d_in[10];
    const float* Wi      = (const float*)d_in[11];
    const float* ln1g_i  = (const float*)d_in[12];
    const float* ln1b_i  = (const float*)d_in[13];
    const float* ln2g_i  = (const float*)d_in[14];
    const float* ln2b_i  = (const float*)d_in[15];
    const int*   rows    = (const int*)d_in[16];
    const int*   cols    = (const int*)d_in[17];
    float* out = (float*)d_out;
    const int nnz = in_sizes[5];
    (void)n_in; (void)out_size;

    __half *hU, *hI, *lU, *lI;
    float *fU, *fI;
    int *ptrU, *ptrI, *posU, *posI, *cntU, *cntI, *chU, *chI;
    int2 *edgeU, *edgeI;
    cudaGetSymbolAddress((void**)&hU, g_hU);
    cudaGetSymbolAddress((void**)&hI, g_hI);
    cudaGetSymbolAddress((void**)&lU, g_lU);
    cudaGetSymbolAddress((void**)&lI, g_lI);
    cudaGetSymbolAddress((void**)&fU, g_fU);
    cudaGetSymbolAddress((void**)&fI, g_fI);
    cudaGetSymbolAddress((void**)&ptrU, g_ptrU);
    cudaGetSymbolAddress((void**)&ptrI, g_ptrI);
    cudaGetSymbolAddress((void**)&posU, g_posU);
    cudaGetSymbolAddress((void**)&posI, g_posI);
    cudaGetSymbolAddress((void**)&cntU, g_cntU);
    cudaGetSymbolAddress((void**)&cntI, g_cntI);
    cudaGetSymbolAddress((void**)&chU, g_chunkU);
    cudaGetSymbolAddress((void**)&chI, g_chunkI);
    cudaGetSymbolAddress((void**)&edgeU, g_edgeU);
    cudaGetSymbolAddress((void**)&edgeI, g_edgeI);

    cudaFuncSetAttribute(gemm_ln_dual,
                         cudaFuncAttributeMaxDynamicSharedMemorySize,
                         D_H * D_H * (int)sizeof(float));

    const int EB = (nnz + 255) / 256;
    const size_t GLN = D_H * D_H * sizeof(float);
    const int NCHU = (N_U + CHUNK - 1) / CHUNK;
    const int NCHI = (N_I + CHUNK - 1) / CHUNK;

    // -------- CSR build (both directions) --------
    zero_int2arr<<<256, 256>>>(cntU, N_U, cntI, N_I);
    hist_kernel<<<EB, 256>>>(rows, cntU, cols, cntI, nnz);
    scan_reduce<<<NCHU, 256>>>(cntU, chU, N_U);
    scan_reduce<<<NCHI, 256>>>(cntI, chI, N_I);
    scan_offsets<<<1, 64>>>(chU, NCHU, chI, NCHI);
    scan_write<<<NCHU, CHUNK>>>(cntU, chU, ptrU, posU, N_U);
    scan_write<<<NCHI, CHUNK>>>(cntI, chI, ptrI, posI, N_I);
    build_both_kernel<<<EB, 256>>>(rows, cols, vals, posU, posI, edgeU, edgeI, nnz);

    // -------- initial projections (features fp16 + acc fp32 in d_out) --------
    fc_leaky_kernel<<<1024, D_H>>>(emb, fc_u_w, fc_u_b, hU, out, N_U);
    fc_leaky_kernel<<<512,  D_H>>>(emb + (size_t)N_U * D_IN, fc_i_w, fc_i_b,
                                   hI, out + (size_t)N_U * D_H, N_I);

    const int SPU = (N_U + 7) / 8;     // 12500
    const int SPI = (N_I + 7) / 8;     // 6250
    const int GA = 512, GB = 1024;     // gemm blocks for I-sized / U-sized jobs

    for (int k = 0; k < N_LAYERS; k++) {
        const float* Wu_k = Wu + (size_t)k * D_H * D_H;
        const float* Wi_k = Wi + (size_t)k * D_H * D_H;
        const float oscale = (k == N_LAYERS - 1) ? (1.f / 3.f) : 1.f;

        // phase 1: fI = A^T * u (N_I rows)  ||  fU = A * i (N_U rows)
        spmm_dual<<<SPI + SPU, 256>>>(ptrI, edgeI, hU, fI, N_I, SPI,
                                      ptrU, edgeU, hI, fU, N_U);
        // phase 2: lI = LN(fI Wu^T) (N_I)  ||  lU = LN(fU Wi^T) (N_U)
        gemm_ln_dual<<<GA + GB, D_H, GLN>>>(fI, Wu_k, ln1g_u + k * D_H, ln1b_u + k * D_H,
                                            lI, N_I, GA,
                                            fU, Wi_k, ln1g_i + k * D_H, ln1b_i + k * D_H,
                                            lU, N_U, GB);
        // phase 3: fU = A * lI (N_U rows)  ||  fI = A^T * lU (N_I rows)
        spmm_dual<<<SPU + SPI, 256>>>(ptrU, edgeU, lI, fU, N_U, SPU,
                                      ptrI, edgeI, lU, fI, N_I);
        // phase 4: u += leaky(LN(fU)); acc_u update  ||  i += leaky(LN(fI)); acc_i
        ln_update_dual<<<SPU + SPI, 256>>>(fU, ln2g_u + k * D_H, ln2b_u + k * D_H,
                                           hU, out, N_U, SPU,
                                           fI, ln2g_i + k * D_H, ln2b_i + k * D_H,
                                           hI, out + (size_t)N_U * D_H, N_I, oscale);
    }
}

// round 5
// speedup vs baseline: 3.1777x; 1.4997x over previous
#include <cuda_runtime.h>
#include <cuda_fp16.h>
#include <cstdint>

#define D_H      128
#define D_IN     64
#define N_U      100000
#define N_I      50000
#define NNZ_MAX  5000000
#define N_LAYERS 2
#define SLOPE_F  0.2f
#define EPS_F    1e-5f
#define CHUNK    1024
#define WPITCH   136   // padded pitch (halfs) for ldmatrix conflict-free rows

// ---------------- scratch (static device globals) ---------------------------
__device__ __align__(256) __half g_hU [(size_t)N_U * D_H];  // user features fp16
__device__ __align__(256) __half g_hI [(size_t)N_I * D_H];  // item features fp16
__device__ __align__(256) __half g_xhU[(size_t)N_U * D_H];  // spmm phase1 out fp16
__device__ __align__(256) __half g_xhI[(size_t)N_I * D_H];
__device__ __align__(256) __half g_lU [(size_t)N_U * D_H];  // lat1 fp16
__device__ __align__(256) __half g_lI [(size_t)N_I * D_H];
__device__ __align__(256) float  g_fU [(size_t)N_U * D_H];  // spmm phase3 out fp32
__device__ __align__(256) float  g_fI [(size_t)N_I * D_H];
__device__ __align__(256) __half g_Wt [4][WPITCH * D_H];    // fp16 W^T, padded: [k][j]

__device__ __align__(256) int2 g_edgeU[NNZ_MAX];
__device__ __align__(256) int2 g_edgeI[NNZ_MAX];
__device__ int g_ptrU[N_U + 1];
__device__ int g_ptrI[N_I + 1];
__device__ int g_posU[N_U];
__device__ int g_posI[N_I];
__device__ int g_cntU[N_U];
__device__ int g_cntI[N_I];
__device__ int g_chunkU[(N_U + CHUNK - 1) / CHUNK];
__device__ int g_chunkI[(N_I + CHUNK - 1) / CHUNK];

__device__ __forceinline__ float leakyf(float x) { return x > 0.f ? x : SLOPE_F * x; }

// ---------------- CSR build ---------------------------------------------------
__global__ void zero_int2arr(int* __restrict__ a, int na, int* __restrict__ b, int nb) {
    int i = blockIdx.x * blockDim.x + threadIdx.x;
    int stride = gridDim.x * blockDim.x;
    for (; i < na; i += stride) a[i] = 0;
    for (i = blockIdx.x * blockDim.x + threadIdx.x; i < nb; i += stride) b[i] = 0;
}

__global__ void hist_kernel(const int* __restrict__ keysA, int* __restrict__ cntA,
                            const int* __restrict__ keysB, int* __restrict__ cntB,
                            int nnz) {
    int i = blockIdx.x * blockDim.x + threadIdx.x;
    int stride = gridDim.x * blockDim.x;
    for (; i < nnz; i += stride) {
        atomicAdd(&cntA[keysA[i]], 1);
        atomicAdd(&cntB[keysB[i]], 1);
    }
}

__global__ void scan_reduce(const int* __restrict__ cnt, int* __restrict__ chunkSum, int n) {
    __shared__ int sw[8];
    const int tid = threadIdx.x;
    const int base = blockIdx.x * CHUNK;
    int s = 0;
    #pragma unroll
    for (int t = 0; t < CHUNK / 256; t++) {
        int idx = base + t * 256 + tid;
        if (idx < n) s += cnt[idx];
    }
    #pragma unroll
    for (int off = 16; off; off >>= 1) s += __shfl_xor_sync(0xffffffffu, s, off);
    if ((tid & 31) == 0) sw[tid >> 5] = s;
    __syncthreads();
    if (tid == 0) {
        int tot = 0;
        #pragma unroll
        for (int w = 0; w < 8; w++) tot += sw[w];
        chunkSum[blockIdx.x] = tot;
    }
}

__global__ void scan_offsets(int* __restrict__ cA, int nA, int* __restrict__ cB, int nB) {
    if (threadIdx.x == 0) {
        int acc = 0;
        for (int c = 0; c < nA; c++) { int v = cA[c]; cA[c] = acc; acc += v; }
    } else if (threadIdx.x == 32) {
        int acc = 0;
        for (int c = 0; c < nB; c++) { int v = cB[c]; cB[c] = acc; acc += v; }
    }
}

__global__ void scan_write(const int* __restrict__ cnt, const int* __restrict__ chunkOff,
                           int* __restrict__ ptr, int* __restrict__ pos, int n) {
    __shared__ int sdata[CHUNK];
    const int tid = threadIdx.x;
    const int i = blockIdx.x * CHUNK + tid;
    int v = (i < n) ? cnt[i] : 0;
    sdata[tid] = v;
    __syncthreads();
    #pragma unroll
    for (int off = 1; off < CHUNK; off <<= 1) {
        int t = (tid >= off) ? sdata[tid - off] : 0;
        __syncthreads();
        sdata[tid] += t;
        __syncthreads();
    }
    if (i < n) {
        int off = chunkOff[blockIdx.x];
        int incl = off + sdata[tid];
        ptr[i + 1] = incl;
        pos[i] = incl - v;
    }
    if (i == 0) ptr[0] = 0;
}

__global__ void build_both_kernel(const int* __restrict__ rows,
                                  const int* __restrict__ cols,
                                  const float* __restrict__ vals,
                                  int* __restrict__ posU, int* __restrict__ posI,
                                  int2* __restrict__ edgeU, int2* __restrict__ edgeI,
                                  int nnz) {
    int i = blockIdx.x * blockDim.x + threadIdx.x;
    int stride = gridDim.x * blockDim.x;
    for (; i < nnz; i += stride) {
        int r = rows[i];
        int c = cols[i];
        int v = __float_as_int(vals[i]);
        int pu_ = atomicAdd(&posU[r], 1);
        edgeU[pu_] = make_int2(c, v);
        int pi_ = atomicAdd(&posI[c], 1);
        edgeI[pi_] = make_int2(r, v);
    }
}

// ---------------- W -> fp16 transposed (all 4 layer matrices, once) ----------
// slot 0: Wu layer0, 1: Wu layer1, 2: Wi layer0, 3: Wi layer1
__global__ void wconvert_kernel(const float* __restrict__ Wu, const float* __restrict__ Wi) {
    int idx = blockIdx.x * blockDim.x + threadIdx.x;          // 4*16384 total
    if (idx >= 4 * D_H * D_H) return;
    int slot = idx >> 14;
    int rem = idx & (D_H * D_H - 1);
    int k = rem >> 7, j = rem & 127;
    const float* W = (slot < 2) ? (Wu + (size_t)slot * D_H * D_H)
                                : (Wi + (size_t)(slot - 2) * D_H * D_H);
    g_Wt[slot][k * WPITCH + j] = __float2half(W[j * D_H + k]);
}

// ---------------- FC + LeakyReLU: half features + fp32 acc init --------------
__global__ void fc_leaky_kernel(const float* __restrict__ emb,
                                const float* __restrict__ W,   // [D_H, D_IN]
                                const float* __restrict__ b,
                                __half* __restrict__ outh,
                                float*  __restrict__ outf,
                                int nrows) {
    __shared__ float sWt[D_IN * D_H];
    __shared__ float sX[4][D_IN];
    const int j = threadIdx.x;
    for (int idx = j; idx < D_IN * D_H; idx += D_H) {
        int k = idx >> 7, jj = idx & 127;
        sWt[idx] = W[jj * D_IN + k];
    }
    const float bj = b[j];
    __syncthreads();

    for (int rbase = blockIdx.x * 4; rbase < nrows; rbase += gridDim.x * 4) {
        for (int t = j; t < 4 * D_IN; t += D_H) {
            int rr = t >> 6, kk = t & 63;
            int row = rbase + rr;
            sX[rr][kk] = (row < nrows) ? emb[(size_t)row * D_IN + kk] : 0.f;
        }
        __syncthreads();
        float a0 = bj, a1 = bj, a2 = bj, a3 = bj;
        #pragma unroll 8
        for (int k = 0; k < D_IN; k++) {
            float w = sWt[k * D_H + j];
            a0 += w * sX[0][k];
            a1 += w * sX[1][k];
            a2 += w * sX[2][k];
            a3 += w * sX[3][k];
        }
        a0 = leakyf(a0); a1 = leakyf(a1); a2 = leakyf(a2); a3 = leakyf(a3);
        if (rbase + 0 < nrows) { outh[(size_t)(rbase+0)*D_H + j] = __float2half(a0); outf[(size_t)(rbase+0)*D_H + j] = a0; }
        if (rbase + 1 < nrows) { outh[(size_t)(rbase+1)*D_H + j] = __float2half(a1); outf[(size_t)(rbase+1)*D_H + j] = a1; }
        if (rbase + 2 < nrows) { outh[(size_t)(rbase+2)*D_H + j] = __float2half(a2); outf[(size_t)(rbase+2)*D_H + j] = a2; }
        if (rbase + 3 < nrows) { outh[(size_t)(rbase+3)*D_H + j] = __float2half(a3); outf[(size_t)(rbase+3)*D_H + j] = a3; }
        __syncthreads();
    }
}

// ---------------- CSR gather SpMM (fp16 gathers; fp16 or fp32 out) -----------
// warp per row; 2 edges per inner step: lanes 0-15 even edge, 16-31 odd edge;
// each lane loads uint4 (8 fp16 features).
template <int OUT_HALF>
__device__ __forceinline__ void spmm_job(const int*  __restrict__ rowptr,
                                         const int2* __restrict__ edge,
                                         const __half* __restrict__ x,
                                         void* __restrict__ yout,
                                         int nrows, int bid) {
    const int lane = threadIdx.x & 31;
    const int half16 = lane >> 4;         // 0: even edges, 1: odd edges
    const int slot = lane & 15;           // feature slice [8*slot .. 8*slot+8)
    const int row  = bid * 8 + ((int)threadIdx.x >> 5);
    if (row >= nrows) return;
    const int beg = rowptr[row];
    const int end = rowptr[row + 1];
    const uint4* __restrict__ x4 = reinterpret_cast<const uint4*>(x);
    float a0 = 0.f, a1 = 0.f, a2 = 0.f, a3 = 0.f, a4 = 0.f, a5 = 0.f, a6 = 0.f, a7 = 0.f;
    for (int base = beg; base < end; base += 32) {
        int e = base + lane;
        int c = 0; float v = 0.f;
        if (e < end) {
            int2 ed = __ldg(edge + e);
            c = ed.x;
            v = __int_as_float(ed.y);
        }
        int m = end - base; if (m > 32) m = 32;
        int mh = (m + 1) >> 1;
        for (int jj = 0; jj < mh; jj++) {
            int srcLane = 2 * jj + half16;
            int   cj = __shfl_sync(0xffffffffu, c, srcLane);
            float vj = __shfl_sync(0xffffffffu, v, srcLane);
            if (srcLane >= m) vj = 0.f;
            uint4 d = __ldg(x4 + (size_t)cj * 16 + slot);
            float2 f0 = __half22float2(*reinterpret_cast<__half2*>(&d.x));
            float2 f1 = __half22float2(*reinterpret_cast<__half2*>(&d.y));
            float2 f2 = __half22float2(*reinterpret_cast<__half2*>(&d.z));
            float2 f3 = __half22float2(*reinterpret_cast<__half2*>(&d.w));
            a0 += vj * f0.x; a1 += vj * f0.y;
            a2 += vj * f1.x; a3 += vj * f1.y;
            a4 += vj * f2.x; a5 += vj * f2.y;
            a6 += vj * f3.x; a7 += vj * f3.y;
        }
    }
    // combine even/odd halves
    a0 += __shfl_xor_sync(0xffffffffu, a0, 16);
    a1 += __shfl_xor_sync(0xffffffffu, a1, 16);
    a2 += __shfl_xor_sync(0xffffffffu, a2, 16);
    a3 += __shfl_xor_sync(0xffffffffu, a3, 16);
    a4 += __shfl_xor_sync(0xffffffffu, a4, 16);
    a5 += __shfl_xor_sync(0xffffffffu, a5, 16);
    a6 += __shfl_xor_sync(0xffffffffu, a6, 16);
    a7 += __shfl_xor_sync(0xffffffffu, a7, 16);
    if (lane < 16) {
        if (OUT_HALF) {
            __half2 h0 = __floats2half2_rn(a0, a1);
            __half2 h1 = __floats2half2_rn(a2, a3);
            __half2 h2 = __floats2half2_rn(a4, a5);
            __half2 h3 = __floats2half2_rn(a6, a7);
            uint4 o;
            o.x = *reinterpret_cast<unsigned int*>(&h0);
            o.y = *reinterpret_cast<unsigned int*>(&h1);
            o.z = *reinterpret_cast<unsigned int*>(&h2);
            o.w = *reinterpret_cast<unsigned int*>(&h3);
            reinterpret_cast<uint4*>(yout)[(size_t)row * 16 + slot] = o;
        } else {
            float4* yp = reinterpret_cast<float4*>(yout) + (size_t)row * 32 + 2 * slot;
            yp[0] = make_float4(a0, a1, a2, a3);
            yp[1] = make_float4(a4, a5, a6, a7);
        }
    }
}

template <int OUT_HALF>
__global__ void spmm_dual(const int*  __restrict__ ptrA, const int2* __restrict__ edgeA,
                          const __half* __restrict__ xA, void* __restrict__ yA,
                          int nA, int blocksA,
                          const int*  __restrict__ ptrB, const int2* __restrict__ edgeB,
                          const __half* __restrict__ xB, void* __restrict__ yB,
                          int nB) {
    if ((int)blockIdx.x < blocksA)
        spmm_job<OUT_HALF>(ptrA, edgeA, xA, yA, nA, blockIdx.x);
    else
        spmm_job<OUT_HALF>(ptrB, edgeB, xB, yB, nB, blockIdx.x - blocksA);
}

// ---------------- tensor-core GEMM (X @ W^T) + LayerNorm ---------------------
// Block: 128 threads (4 warps). M-tile = 16 rows; warp w owns cols [32w,32w+32).
// B fragments (weights) preloaded to registers once per block; X tiles streamed.
__device__ __forceinline__ void gemm_ln_mma_job(const __half* __restrict__ X,
                                                const __half* __restrict__ Wt, // [k][j] pitch WPITCH
                                                const float* __restrict__ g,
                                                const float* __restrict__ b,
                                                __half* __restrict__ out,
                                                int nrows, int bid, int nblocks,
                                                __half* sW, __half* sX) {
    const int tid  = threadIdx.x;
    const int w    = tid >> 5;
    const int lane = tid & 31;

    __shared__ float sSum[16][4];
    __shared__ float sSq [16][4];
    __shared__ float sMu [16];
    __shared__ float sRs [16];

    // ---- load W into smem (with padding preserved), coalesced uint4 copy ----
    {
        const uint4* src = reinterpret_cast<const uint4*>(Wt);
        uint4* dst = reinterpret_cast<uint4*>(sW);
        const int n16 = D_H * WPITCH / 8;    // uint4 = 8 halfs
        for (int i = tid; i < n16; i += 128) dst[i] = src[i];
    }
    __syncthreads();

    // ---- preload B fragments: bfr[kc][ncl][2], warp cols = w*32 + ncl*8 ----
    unsigned int bfr[8][4][2];
    {
        unsigned int swBase = (unsigned int)__cvta_generic_to_shared(sW);
        #pragma unroll
        for (int kc = 0; kc < 8; kc++) {
            #pragma unroll
            for (int ncl = 0; ncl < 4; ncl++) {
                int krow = kc * 16 + (lane & 15);
                int col  = w * 32 + ncl * 8;
                unsigned int addr = swBase + (unsigned int)((krow * WPITCH + col) * 2);
                asm volatile("ldmatrix.sync.aligned.m8n8.x2.trans.shared.b16 {%0,%1}, [%2];"
                             : "=r"(bfr[kc][ncl][0]), "=r"(bfr[kc][ncl][1]) : "r"(addr));
            }
        }
    }

    // per-thread gamma/beta for owned columns
    float2 gv[4], bv[4];
    #pragma unroll
    for (int ncl = 0; ncl < 4; ncl++) {
        int j = w * 32 + ncl * 8 + (lane & 3) * 2;
        gv[ncl] = *reinterpret_cast<const float2*>(g + j);
        bv[ncl] = *reinterpret_cast<const float2*>(b + j);
    }

    const int ntiles = (nrows + 15) >> 4;
    unsigned int sxBase = (unsigned int)__cvta_generic_to_shared(sX);

    for (int tile = bid; tile < ntiles; tile += nblocks) {
        const int rowbase = tile * 16;
        // ---- load X tile: 16 rows x 128 halfs, pitch WPITCH ----
        {
            int r = tid >> 3;            // 0..15
            int p = tid & 7;             // 0..7, two uint4 chunks each
            int grow = rowbase + r;
            uint4 z = make_uint4(0, 0, 0, 0);
            const uint4* xr = reinterpret_cast<const uint4*>(X) + (size_t)grow * 16;
            uint4* dst = reinterpret_cast<uint4*>(sX + r * WPITCH);
            if (grow < nrows) {
                dst[p]     = __ldg(xr + p);
                dst[p + 8] = __ldg(xr + p + 8);
            } else {
                dst[p] = z; dst[p + 8] = z;
            }
        }
        __syncthreads();

        // ---- mma over K ----
        float acc[4][4];
        #pragma unroll
        for (int ncl = 0; ncl < 4; ncl++)
            #pragma unroll
            for (int q = 0; q < 4; q++) acc[ncl][q] = 0.f;

        #pragma unroll
        for (int kc = 0; kc < 8; kc++) {
            unsigned int a0, a1, a2, a3;
            int arow = (lane & 7) + ((lane >> 3) & 1) * 8;
            int acol = kc * 16 + ((lane >> 4) & 1) * 8;
            unsigned int addr = sxBase + (unsigned int)((arow * WPITCH + acol) * 2);
            asm volatile("ldmatrix.sync.aligned.m8n8.x4.shared.b16 {%0,%1,%2,%3}, [%4];"
                         : "=r"(a0), "=r"(a1), "=r"(a2), "=r"(a3) : "r"(addr));
            #pragma unroll
            for (int ncl = 0; ncl < 4; ncl++) {
                asm volatile("mma.sync.aligned.m16n8k16.row.col.f32.f16.f16.f32 "
                             "{%0,%1,%2,%3}, {%4,%5,%6,%7}, {%8,%9}, {%0,%1,%2,%3};"
                             : "+f"(acc[ncl][0]), "+f"(acc[ncl][1]),
                               "+f"(acc[ncl][2]), "+f"(acc[ncl][3])
                             : "r"(a0), "r"(a1), "r"(a2), "r"(a3),
                               "r"(bfr[kc][ncl][0]), "r"(bfr[kc][ncl][1]));
            }
        }

        // ---- LayerNorm: fragment rows r0 = lane>>2, r1 = r0+8 ----
        float s0 = 0.f, s1 = 0.f, q0 = 0.f, q1 = 0.f;
        #pragma unroll
        for (int ncl = 0; ncl < 4; ncl++) {
            s0 += acc[ncl][0] + acc[ncl][1];
            s1 += acc[ncl][2] + acc[ncl][3];
            q0 += acc[ncl][0] * acc[ncl][0] + acc[ncl][1] * acc[ncl][1];
            q1 += acc[ncl][2] * acc[ncl][2] + acc[ncl][3] * acc[ncl][3];
        }
        s0 += __shfl_xor_sync(0xffffffffu, s0, 1);
        s0 += __shfl_xor_sync(0xffffffffu, s0, 2);
        s1 += __shfl_xor_sync(0xffffffffu, s1, 1);
        s1 += __shfl_xor_sync(0xffffffffu, s1, 2);
        q0 += __shfl_xor_sync(0xffffffffu, q0, 1);
        q0 += __shfl_xor_sync(0xffffffffu, q0, 2);
        q1 += __shfl_xor_sync(0xffffffffu, q1, 1);
        q1 += __shfl_xor_sync(0xffffffffu, q1, 2);
        if ((lane & 3) == 0) {
            int r = lane >> 2;
            sSum[r][w] = s0; sSum[r + 8][w] = s1;
            sSq [r][w] = q0; sSq [r + 8][w] = q1;
        }
        __syncthreads();
        if (tid < 16) {
            float s = sSum[tid][0] + sSum[tid][1] + sSum[tid][2] + sSum[tid][3];
            float q = sSq[tid][0] + sSq[tid][1] + sSq[tid][2] + sSq[tid][3];
            float mu = s * (1.f / 128.f);
            float var = q * (1.f / 128.f) - mu * mu;
            sMu[tid] = mu;
            sRs[tid] = rsqrtf(var + EPS_F);
        }
        __syncthreads();

        {
            int r0 = lane >> 2;
            float mu0 = sMu[r0],     rs0 = sRs[r0];
            float mu1 = sMu[r0 + 8], rs1 = sRs[r0 + 8];
            int grow0 = rowbase + r0;
            int grow1 = rowbase + r0 + 8;
            #pragma unroll
            for (int ncl = 0; ncl < 4; ncl++) {
                int j = w * 32 + ncl * 8 + (lane & 3) * 2;
                if (grow0 < nrows) {
                    __half2 o = __floats2half2_rn(
                        (acc[ncl][0] - mu0) * rs0 * gv[ncl].x + bv[ncl].x,
                        (acc[ncl][1] - mu0) * rs0 * gv[ncl].y + bv[ncl].y);
                    *reinterpret_cast<__half2*>(out + (size_t)grow0 * D_H + j) = o;
                }
                if (grow1 < nrows) {
                    __half2 o = __floats2half2_rn(
                        (acc[ncl][2] - mu1) * rs1 * gv[ncl].x + bv[ncl].x,
                        (acc[ncl][3] - mu1) * rs1 * gv[ncl].y + bv[ncl].y);
                    *reinterpret_cast<__half2*>(out + (size_t)grow1 * D_H + j) = o;
                }
            }
        }
        __syncthreads();
    }
}

__global__ void gemm_ln_mma_dual(const __half* __restrict__ XA, const __half* __restrict__ WtA,
                                 const float* __restrict__ gA, const float* __restrict__ bA,
                                 __half* __restrict__ outA, int nA, int blocksA,
                                 const __half* __restrict__ XB, const __half* __restrict__ WtB,
                                 const float* __restrict__ gB, const float* __restrict__ bB,
                                 __half* __restrict__ outB, int nB, int blocksB) {
    extern __shared__ __half smem[];
    __half* sW = smem;                       // D_H * WPITCH halfs
    __half* sX = smem + D_H * WPITCH;        // 16 * WPITCH halfs
    if ((int)blockIdx.x < blocksA)
        gemm_ln_mma_job(XA, WtA, gA, bA, outA, nA, blockIdx.x, blocksA, sW, sX);
    else
        gemm_ln_mma_job(XB, WtB, gB, bB, outB, nB, blockIdx.x - blocksA, blocksB, sW, sX);
}

// ---------------- LN + leaky + residual/accumulator update -------------------
__device__ __forceinline__ void ln_update_job(const float* __restrict__ y,
                                              const float* __restrict__ g,
                                              const float* __restrict__ b,
                                              __half* __restrict__ feat,
                                              float* __restrict__ acc,
                                              int nrows, int bid, float oscale) {
    const int lane = threadIdx.x & 31;
    const int row = bid * 8 + ((int)threadIdx.x >> 5);
    if (row >= nrows) return;
    const float4 gv = *(reinterpret_cast<const float4*>(g) + lane);
    const float4 bv = *(reinterpret_cast<const float4*>(b) + lane);
    float4 v = __ldg(reinterpret_cast<const float4*>(y + (size_t)row * D_H) + lane);
    float s = v.x + v.y + v.z + v.w;
    float q = v.x*v.x + v.y*v.y + v.z*v.z + v.w*v.w;
    #pragma unroll
    for (int off = 16; off; off >>= 1) {
        s += __shfl_xor_sync(0xffffffffu, s, off);
        q += __shfl_xor_sync(0xffffffffu, q, off);
    }
    const float inv = 1.f / (float)D_H;
    float mu = s * inv;
    float rs = rsqrtf(q * inv - mu * mu + EPS_F);
    float4 h;
    h.x = leakyf((v.x - mu) * rs * gv.x + bv.x);
    h.y = leakyf((v.y - mu) * rs * gv.y + bv.y);
    h.z = leakyf((v.z - mu) * rs * gv.z + bv.z);
    h.w = leakyf((v.w - mu) * rs * gv.w + bv.w);
    uint2* fp = reinterpret_cast<uint2*>(feat) + (size_t)row * 32 + lane;
    uint2 fd = *fp;
    float2 ff0 = __half22float2(*reinterpret_cast<__half2*>(&fd.x));
    float2 ff1 = __half22float2(*reinterpret_cast<__half2*>(&fd.y));
    ff0.x += h.x; ff0.y += h.y; ff1.x += h.z; ff1.y += h.w;
    __half2 o0 = __floats2half2_rn(ff0.x, ff0.y);
    __half2 o1 = __floats2half2_rn(ff1.x, ff1.y);
    fd.x = *reinterpret_cast<unsigned int*>(&o0);
    fd.y = *reinterpret_cast<unsigned int*>(&o1);
    *fp = fd;
    float4* ap = reinterpret_cast<float4*>(acc) + (size_t)row * 32 + lane;
    float4 av = *ap;
    av.x = (av.x + h.x) * oscale;
    av.y = (av.y + h.y) * oscale;
    av.z = (av.z + h.z) * oscale;
    av.w = (av.w + h.w) * oscale;
    *ap = av;
}

__global__ void ln_update_dual(const float* __restrict__ yA,
                               const float* __restrict__ gA, const float* __restrict__ bA,
                               __half* __restrict__ featA, float* __restrict__ accA,
                               int nA, int blocksA,
                               const float* __restrict__ yB,
                               const float* __restrict__ gB, const float* __restrict__ bB,
                               __half* __restrict__ featB, float* __restrict__ accB,
                               int nB, float oscale) {
    if ((int)blockIdx.x < blocksA)
        ln_update_job(yA, gA, bA, featA, accA, nA, blockIdx.x, oscale);
    else
        ln_update_job(yB, gB, bB, featB, accB, nB, blockIdx.x - blocksA, oscale);
}

// ---------------- launch ------------------------------------------------------
extern "C" void kernel_launch(void* const* d_in, const int* in_sizes, int n_in,
                              void* d_out, int out_size) {
    const float* emb     = (const float*)d_in[0];
    const float* fc_u_w  = (const float*)d_in[1];
    const float* fc_u_b  = (const float*)d_in[2];
    const float* fc_i_w  = (const float*)d_in[3];
    const float* fc_i_b  = (const float*)d_in[4];
    const float* vals    = (const float*)d_in[5];
    const float* Wu      = (const float*)d_in[6];
    const float* ln1g_u  = (const float*)d_in[7];
    const float* ln1b_u  = (const float*)d_in[8];
    const float* ln2g_u  = (const float*)d_in[9];
    const float* ln2b_u  = (const float*)d_in[10];
    const float* Wi      = (const float*)d_in[11];
    const float* ln1g_i  = (const float*)d_in[12];
    const float* ln1b_i  = (const float*)d_in[13];
    const float* ln2g_i  = (const float*)d_in[14];
    const float* ln2b_i  = (const float*)d_in[15];
    const int*   rows    = (const int*)d_in[16];
    const int*   cols    = (const int*)d_in[17];
    float* out = (float*)d_out;
    const int nnz = in_sizes[5];
    (void)n_in; (void)out_size;

    __half *hU, *hI, *xhU, *xhI, *lU, *lI, *Wt0;
    float *fU, *fI;
    int *ptrU, *ptrI, *posU, *posI, *cntU, *cntI, *chU, *chI;
    int2 *edgeU, *edgeI;
    cudaGetSymbolAddress((void**)&hU, g_hU);
    cudaGetSymbolAddress((void**)&hI, g_hI);
    cudaGetSymbolAddress((void**)&xhU, g_xhU);
    cudaGetSymbolAddress((void**)&xhI, g_xhI);
    cudaGetSymbolAddress((void**)&lU, g_lU);
    cudaGetSymbolAddress((void**)&lI, g_lI);
    cudaGetSymbolAddress((void**)&Wt0, g_Wt);
    cudaGetSymbolAddress((void**)&fU, g_fU);
    cudaGetSymbolAddress((void**)&fI, g_fI);
    cudaGetSymbolAddress((void**)&ptrU, g_ptrU);
    cudaGetSymbolAddress((void**)&ptrI, g_ptrI);
    cudaGetSymbolAddress((void**)&posU, g_posU);
    cudaGetSymbolAddress((void**)&posI, g_posI);
    cudaGetSymbolAddress((void**)&cntU, g_cntU);
    cudaGetSymbolAddress((void**)&cntI, g_cntI);
    cudaGetSymbolAddress((void**)&chU, g_chunkU);
    cudaGetSymbolAddress((void**)&chI, g_chunkI);
    cudaGetSymbolAddress((void**)&edgeU, g_edgeU);
    cudaGetSymbolAddress((void**)&edgeI, g_edgeI);

    const int EB = (nnz + 255) / 256;
    const int NCHU = (N_U + CHUNK - 1) / CHUNK;
    const int NCHI = (N_I + CHUNK - 1) / CHUNK;
    const size_t GEMM_SMEM = (size_t)(D_H + 16) * WPITCH * sizeof(__half);

    // -------- CSR build (both directions) --------
    zero_int2arr<<<256, 256>>>(cntU, N_U, cntI, N_I);
    hist_kernel<<<EB, 256>>>(rows, cntU, cols, cntI, nnz);
    scan_reduce<<<NCHU, 256>>>(cntU, chU, N_U);
    scan_reduce<<<NCHI, 256>>>(cntI, chI, N_I);
    scan_offsets<<<1, 64>>>(chU, NCHU, chI, NCHI);
    scan_write<<<NCHU, CHUNK>>>(cntU, chU, ptrU, posU, N_U);
    scan_write<<<NCHI, CHUNK>>>(cntI, chI, ptrI, posI, N_I);
    build_both_kernel<<<EB, 256>>>(rows, cols, vals, posU, posI, edgeU, edgeI, nnz);

    // -------- weights -> fp16 transposed (all layers, once) --------
    wconvert_kernel<<<(4 * D_H * D_H + 255) / 256, 256>>>(Wu, Wi);

    // -------- initial projections --------
    fc_leaky_kernel<<<1024, D_H>>>(emb, fc_u_w, fc_u_b, hU, out, N_U);
    fc_leaky_kernel<<<512,  D_H>>>(emb + (size_t)N_U * D_IN, fc_i_w, fc_i_b,
                                   hI, out + (size_t)N_U * D_H, N_I);

    const int SPU = (N_U + 7) / 8;
    const int SPI = (N_I + 7) / 8;
    const int GA = 512, GB = 1024;   // gemm dual grid split

    for (int k = 0; k < N_LAYERS; k++) {
        const __half* WtU_k = Wt0 + (size_t)k * WPITCH * D_H;            // slots 0,1: Wu
        const __half* WtI_k = Wt0 + (size_t)(2 + k) * WPITCH * D_H;      // slots 2,3: Wi
        const float oscale = (k == N_LAYERS - 1) ? (1.f / 3.f) : 1.f;

        // phase 1: xhI = A^T u (N_I)  ||  xhU = A i (N_U)   [fp16 out]
        spmm_dual<1><<<SPI + SPU, 256>>>(ptrI, edgeI, hU, xhI, N_I, SPI,
                                         ptrU, edgeU, hI, xhU, N_U);
        // phase 2: lI = LN(xhI Wu^T)  ||  lU = LN(xhU Wi^T)  [tensor cores]
        gemm_ln_mma_dual<<<GA + GB, 128, GEMM_SMEM>>>(
            xhI, WtU_k, ln1g_u + k * D_H, ln1b_u + k * D_H, lI, N_I, GA,
            xhU, WtI_k, ln1g_i + k * D_H, ln1b_i + k * D_H, lU, N_U, GB);
        // phase 3: fU = A lI (N_U)  ||  fI = A^T lU (N_I)   [fp32 out]
        spmm_dual<0><<<SPU + SPI, 256>>>(ptrU, edgeU, lI, fU, N_U, SPU,
                                         ptrI, edgeI, lU, fI, N_I);
        // phase 4: update u / acc_u  ||  i / acc_i
        ln_update_dual<<<SPU + SPI, 256>>>(fU, ln2g_u + k * D_H, ln2b_u + k * D_H,
                                           hU, out, N_U, SPU,
                                           fI, ln2g_i + k * D_H, ln2b_i + k * D_H,
                                           hI, out + (size_t)N_U * D_H, N_I, oscale);
    }
}

// round 6
// speedup vs baseline: 3.3943x; 1.0681x over previous
#include <cuda_runtime.h>
#include <cuda_fp16.h>
#include <cstdint>

#define D_H      128
#define D_IN     64
#define N_U      100000
#define N_I      50000
#define NNZ_MAX  5000000
#define N_LAYERS 2
#define SLOPE_F  0.2f
#define EPS_F    1e-5f
#define CHUNK    1024
#define WPITCH   136   // padded pitch (halfs) for ldmatrix conflict-free rows

// ---------------- scratch (static device globals) ---------------------------
__device__ __align__(256) __half g_hU [(size_t)N_U * D_H];  // user features fp16
__device__ __align__(256) __half g_hI [(size_t)N_I * D_H];  // item features fp16
__device__ __align__(256) __half g_xhU[(size_t)N_U * D_H];  // spmm phase1 out fp16
__device__ __align__(256) __half g_xhI[(size_t)N_I * D_H];
__device__ __align__(256) __half g_lU [(size_t)N_U * D_H];  // lat1 fp16
__device__ __align__(256) __half g_lI [(size_t)N_I * D_H];
__device__ __align__(256) __half g_Wt [4][WPITCH * D_H];    // fp16 W^T, padded: [k][j]

__device__ __align__(256) int2 g_edgeU[NNZ_MAX];
__device__ __align__(256) int2 g_edgeI[NNZ_MAX];
__device__ int g_ptrU[N_U + 1];
__device__ int g_ptrI[N_I + 1];
__device__ int g_posU[N_U];
__device__ int g_posI[N_I];
__device__ int g_cntU[N_U];
__device__ int g_cntI[N_I];
__device__ int g_chunkU[(N_U + CHUNK - 1) / CHUNK];
__device__ int g_chunkI[(N_I + CHUNK - 1) / CHUNK];

__device__ __forceinline__ float leakyf(float x) { return x > 0.f ? x : SLOPE_F * x; }

// ---------------- CSR build ---------------------------------------------------
__global__ void zero_int2arr(int* __restrict__ a, int na, int* __restrict__ b, int nb) {
    int i = blockIdx.x * blockDim.x + threadIdx.x;
    int stride = gridDim.x * blockDim.x;
    for (; i < na; i += stride) a[i] = 0;
    for (i = blockIdx.x * blockDim.x + threadIdx.x; i < nb; i += stride) b[i] = 0;
}

// ---------------- FC + LeakyReLU (job form, 128 threads/block) ----------------
__device__ __forceinline__ void fc_leaky_job(const float* __restrict__ emb,
                                             const float* __restrict__ W,   // [D_H, D_IN]
                                             const float* __restrict__ b,
                                             __half* __restrict__ outh,
                                             float*  __restrict__ outf,
                                             int nrows, int bid, int nblocks) {
    __shared__ float sWt[D_IN * D_H];
    __shared__ float sX[4][D_IN];
    const int j = threadIdx.x;
    for (int idx = j; idx < D_IN * D_H; idx += D_H) {
        int k = idx >> 7, jj = idx & 127;
        sWt[idx] = W[jj * D_IN + k];
    }
    const float bj = b[j];
    __syncthreads();

    for (int rbase = bid * 4; rbase < nrows; rbase += nblocks * 4) {
        for (int t = j; t < 4 * D_IN; t += D_H) {
            int rr = t >> 6, kk = t & 63;
            int row = rbase + rr;
            sX[rr][kk] = (row < nrows) ? emb[(size_t)row * D_IN + kk] : 0.f;
        }
        __syncthreads();
        float a0 = bj, a1 = bj, a2 = bj, a3 = bj;
        #pragma unroll 8
        for (int k = 0; k < D_IN; k++) {
            float w = sWt[k * D_H + j];
            a0 += w * sX[0][k];
            a1 += w * sX[1][k];
            a2 += w * sX[2][k];
            a3 += w * sX[3][k];
        }
        a0 = leakyf(a0); a1 = leakyf(a1); a2 = leakyf(a2); a3 = leakyf(a3);
        if (rbase + 0 < nrows) { outh[(size_t)(rbase+0)*D_H + j] = __float2half(a0); outf[(size_t)(rbase+0)*D_H + j] = a0; }
        if (rbase + 1 < nrows) { outh[(size_t)(rbase+1)*D_H + j] = __float2half(a1); outf[(size_t)(rbase+1)*D_H + j] = a1; }
        if (rbase + 2 < nrows) { outh[(size_t)(rbase+2)*D_H + j] = __float2half(a2); outf[(size_t)(rbase+2)*D_H + j] = a2; }
        if (rbase + 3 < nrows) { outh[(size_t)(rbase+3)*D_H + j] = __float2half(a3); outf[(size_t)(rbase+3)*D_H + j] = a3; }
        __syncthreads();
    }
}

// ---------------- fused prep: histogram || fc_u || fc_i ----------------------
// blocks [0, HB): histogram; [HB, HB+FU): fc_u; [HB+FU, HB+FU+FI): fc_i
#define HB 2048
#define FU 1024
#define FI 512
__global__ void prep_fused(const int* __restrict__ rows, const int* __restrict__ cols,
                           int* __restrict__ cntU, int* __restrict__ cntI, int nnz,
                           const float* __restrict__ emb,
                           const float* __restrict__ fc_u_w, const float* __restrict__ fc_u_b,
                           const float* __restrict__ fc_i_w, const float* __restrict__ fc_i_b,
                           __half* __restrict__ hU, __half* __restrict__ hI,
                           float* __restrict__ accU, float* __restrict__ accI) {
    const int bid = blockIdx.x;
    if (bid < HB) {
        int i = bid * 128 + threadIdx.x;
        int stride = HB * 128;
        for (; i < nnz; i += stride) {
            atomicAdd(&cntU[rows[i]], 1);
            atomicAdd(&cntI[cols[i]], 1);
        }
    } else if (bid < HB + FU) {
        fc_leaky_job(emb, fc_u_w, fc_u_b, hU, accU, N_U, bid - HB, FU);
    } else {
        fc_leaky_job(emb + (size_t)N_U * D_IN, fc_i_w, fc_i_b, hI, accI, N_I,
                     bid - HB - FU, FI);
    }
}

// scan phase 1 (dual): per-chunk sums
__global__ void scan_reduce_dual(const int* __restrict__ cntU, int* __restrict__ chU, int nchU,
                                 const int* __restrict__ cntI, int* __restrict__ chI) {
    __shared__ int sw[8];
    const int tid = threadIdx.x;
    const int* cnt;
    int* chunkSum;
    int n, cb;
    if ((int)blockIdx.x < nchU) { cnt = cntU; chunkSum = chU; n = N_U; cb = blockIdx.x; }
    else                        { cnt = cntI; chunkSum = chI; n = N_I; cb = blockIdx.x - nchU; }
    const int base = cb * CHUNK;
    int s = 0;
    #pragma unroll
    for (int t = 0; t < CHUNK / 256; t++) {
        int idx = base + t * 256 + tid;
        if (idx < n) s += cnt[idx];
    }
    #pragma unroll
    for (int off = 16; off; off >>= 1) s += __shfl_xor_sync(0xffffffffu, s, off);
    if ((tid & 31) == 0) sw[tid >> 5] = s;
    __syncthreads();
    if (tid == 0) {
        int tot = 0;
        #pragma unroll
        for (int w = 0; w < 8; w++) tot += sw[w];
        chunkSum[cb] = tot;
    }
}

__global__ void scan_offsets(int* __restrict__ cA, int nA, int* __restrict__ cB, int nB) {
    if (threadIdx.x == 0) {
        int acc = 0;
        for (int c = 0; c < nA; c++) { int v = cA[c]; cA[c] = acc; acc += v; }
    } else if (threadIdx.x == 32) {
        int acc = 0;
        for (int c = 0; c < nB; c++) { int v = cB[c]; cB[c] = acc; acc += v; }
    }
}

// scan phase 3 (dual): per-chunk inclusive scan + offset; write ptr and pos
__global__ void scan_write_dual(const int* __restrict__ cntU, const int* __restrict__ chU,
                                int* __restrict__ ptrU, int* __restrict__ posU, int nchU,
                                const int* __restrict__ cntI, const int* __restrict__ chI,
                                int* __restrict__ ptrI, int* __restrict__ posI) {
    __shared__ int sdata[CHUNK];
    const int tid = threadIdx.x;
    const int* cnt; const int* chunkOff;
    int* ptr; int* pos; int n, cb;
    if ((int)blockIdx.x < nchU) { cnt = cntU; chunkOff = chU; ptr = ptrU; pos = posU; n = N_U; cb = blockIdx.x; }
    else                        { cnt = cntI; chunkOff = chI; ptr = ptrI; pos = posI; n = N_I; cb = blockIdx.x - nchU; }
    const int i = cb * CHUNK + tid;
    int v = (i < n) ? cnt[i] : 0;
    sdata[tid] = v;
    __syncthreads();
    #pragma unroll
    for (int off = 1; off < CHUNK; off <<= 1) {
        int t = (tid >= off) ? sdata[tid - off] : 0;
        __syncthreads();
        sdata[tid] += t;
        __syncthreads();
    }
    if (i < n) {
        int off = chunkOff[cb];
        int incl = off + sdata[tid];
        ptr[i + 1] = incl;
        pos[i] = incl - v;
    }
    if (i == 0) ptr[0] = 0;
}

__global__ void build_both_kernel(const int* __restrict__ rows,
                                  const int* __restrict__ cols,
                                  const float* __restrict__ vals,
                                  int* __restrict__ posU, int* __restrict__ posI,
                                  int2* __restrict__ edgeU, int2* __restrict__ edgeI,
                                  int nnz) {
    int i = blockIdx.x * blockDim.x + threadIdx.x;
    int stride = gridDim.x * blockDim.x;
    for (; i < nnz; i += stride) {
        int r = rows[i];
        int c = cols[i];
        int v = __float_as_int(vals[i]);
        int pu_ = atomicAdd(&posU[r], 1);
        edgeU[pu_] = make_int2(c, v);
        int pi_ = atomicAdd(&posI[c], 1);
        edgeI[pi_] = make_int2(r, v);
    }
}

// ---------------- W -> fp16 transposed (all 4 layer matrices, once) ----------
__global__ void wconvert_kernel(const float* __restrict__ Wu, const float* __restrict__ Wi) {
    int idx = blockIdx.x * blockDim.x + threadIdx.x;
    if (idx >= 4 * D_H * D_H) return;
    int slot = idx >> 14;
    int rem = idx & (D_H * D_H - 1);
    int k = rem >> 7, j = rem & 127;
    const float* W = (slot < 2) ? (Wu + (size_t)slot * D_H * D_H)
                                : (Wi + (size_t)(slot - 2) * D_H * D_H);
    g_Wt[slot][k * WPITCH + j] = __float2half(W[j * D_H + k]);
}

// ---------------- shared spmm accumulation core -------------------------------
// Returns combined row accumulators in a[0..7] (all lanes hold slot=lane&15 values)
__device__ __forceinline__ void spmm_accum(const int* __restrict__ rowptr,
                                           const int2* __restrict__ edge,
                                           const __half* __restrict__ x,
                                           int row, int lane, int half16, int slot,
                                           float* a) {
    const int beg = rowptr[row];
    const int end = rowptr[row + 1];
    const uint4* __restrict__ x4 = reinterpret_cast<const uint4*>(x);
    #pragma unroll
    for (int q = 0; q < 8; q++) a[q] = 0.f;
    for (int base = beg; base < end; base += 32) {
        int e = base + lane;
        int c = 0; float v = 0.f;
        if (e < end) {
            int2 ed = __ldg(edge + e);
            c = ed.x;
            v = __int_as_float(ed.y);
        }
        int m = end - base; if (m > 32) m = 32;
        int mh = (m + 1) >> 1;
        for (int jj = 0; jj < mh; jj++) {
            int srcLane = 2 * jj + half16;
            int   cj = __shfl_sync(0xffffffffu, c, srcLane);
            float vj = __shfl_sync(0xffffffffu, v, srcLane);
            if (srcLane >= m) vj = 0.f;
            uint4 d = __ldg(x4 + (size_t)cj * 16 + slot);
            float2 f0 = __half22float2(*reinterpret_cast<__half2*>(&d.x));
            float2 f1 = __half22float2(*reinterpret_cast<__half2*>(&d.y));
            float2 f2 = __half22float2(*reinterpret_cast<__half2*>(&d.z));
            float2 f3 = __half22float2(*reinterpret_cast<__half2*>(&d.w));
            a[0] += vj * f0.x; a[1] += vj * f0.y;
            a[2] += vj * f1.x; a[3] += vj * f1.y;
            a[4] += vj * f2.x; a[5] += vj * f2.y;
            a[6] += vj * f3.x; a[7] += vj * f3.y;
        }
    }
    #pragma unroll
    for (int q = 0; q < 8; q++)
        a[q] += __shfl_xor_sync(0xffffffffu, a[q], 16);
}

// ---------------- phase-1 SpMM: fp16 output -----------------------------------
__device__ __forceinline__ void spmm_h_job(const int*  __restrict__ rowptr,
                                           const int2* __restrict__ edge,
                                           const __half* __restrict__ x,
                                           __half* __restrict__ yout,
                                           int nrows, int bid) {
    const int lane = threadIdx.x & 31;
    const int half16 = lane >> 4;
    const int slot = lane & 15;
    const int row  = bid * 8 + ((int)threadIdx.x >> 5);
    if (row >= nrows) return;
    float a[8];
    spmm_accum(rowptr, edge, x, row, lane, half16, slot, a);
    if (lane < 16) {
        __half2 h0 = __floats2half2_rn(a[0], a[1]);
        __half2 h1 = __floats2half2_rn(a[2], a[3]);
        __half2 h2 = __floats2half2_rn(a[4], a[5]);
        __half2 h3 = __floats2half2_rn(a[6], a[7]);
        uint4 o;
        o.x = *reinterpret_cast<unsigned int*>(&h0);
        o.y = *reinterpret_cast<unsigned int*>(&h1);
        o.z = *reinterpret_cast<unsigned int*>(&h2);
        o.w = *reinterpret_cast<unsigned int*>(&h3);
        reinterpret_cast<uint4*>(yout)[(size_t)row * 16 + slot] = o;
    }
}

__global__ void spmm_h_dual(const int*  __restrict__ ptrA, const int2* __restrict__ edgeA,
                            const __half* __restrict__ xA, __half* __restrict__ yA,
                            int nA, int blocksA,
                            const int*  __restrict__ ptrB, const int2* __restrict__ edgeB,
                            const __half* __restrict__ xB, __half* __restrict__ yB,
                            int nB) {
    if ((int)blockIdx.x < blocksA)
        spmm_h_job(ptrA, edgeA, xA, yA, nA, blockIdx.x);
    else
        spmm_h_job(ptrB, edgeB, xB, yB, nB, blockIdx.x - blocksA);
}

// ---------------- phase-3+4 fused: SpMM -> LN -> leaky -> feat+=, acc update --
__device__ __forceinline__ void spmm_ln_job(const int*  __restrict__ rowptr,
                                            const int2* __restrict__ edge,
                                            const __half* __restrict__ x,
                                            const float* __restrict__ g,
                                            const float* __restrict__ b,
                                            __half* __restrict__ feat,
                                            float* __restrict__ acc,
                                            int nrows, int bid, float oscale) {
    const int lane = threadIdx.x & 31;
    const int half16 = lane >> 4;
    const int slot = lane & 15;
    const int row  = bid * 8 + ((int)threadIdx.x >> 5);
    if (row >= nrows) return;
    float a[8];
    spmm_accum(rowptr, edge, x, row, lane, half16, slot, a);

    // LN stats across the 16 slots (both 16-lane groups hold identical data)
    float s = 0.f, q = 0.f;
    #pragma unroll
    for (int t = 0; t < 8; t++) { s += a[t]; q += a[t] * a[t]; }
    #pragma unroll
    for (int off = 8; off; off >>= 1) {
        s += __shfl_xor_sync(0xffffffffu, s, off);
        q += __shfl_xor_sync(0xffffffffu, q, off);
    }
    const float inv = 1.f / (float)D_H;
    float mu = s * inv;
    float rs = rsqrtf(q * inv - mu * mu + EPS_F);

    if (lane < 16) {
        const float4 g0 = __ldg(reinterpret_cast<const float4*>(g) + 2 * slot);
        const float4 g1 = __ldg(reinterpret_cast<const float4*>(g) + 2 * slot + 1);
        const float4 b0 = __ldg(reinterpret_cast<const float4*>(b) + 2 * slot);
        const float4 b1 = __ldg(reinterpret_cast<const float4*>(b) + 2 * slot + 1);
        float h[8];
        h[0] = leakyf((a[0] - mu) * rs * g0.x + b0.x);
        h[1] = leakyf((a[1] - mu) * rs * g0.y + b0.y);
        h[2] = leakyf((a[2] - mu) * rs * g0.z + b0.z);
        h[3] = leakyf((a[3] - mu) * rs * g0.w + b0.w);
        h[4] = leakyf((a[4] - mu) * rs * g1.x + b1.x);
        h[5] = leakyf((a[5] - mu) * rs * g1.y + b1.y);
        h[6] = leakyf((a[6] - mu) * rs * g1.z + b1.z);
        h[7] = leakyf((a[7] - mu) * rs * g1.w + b1.w);
        // feat (fp16) += h
        uint4* fp = reinterpret_cast<uint4*>(feat) + (size_t)row * 16 + slot;
        uint4 fd = *fp;
        float2 f0 = __half22float2(*reinterpret_cast<__half2*>(&fd.x));
        float2 f1 = __half22float2(*reinterpret_cast<__half2*>(&fd.y));
        float2 f2 = __half22float2(*reinterpret_cast<__half2*>(&fd.z));
        float2 f3 = __half22float2(*reinterpret_cast<__half2*>(&fd.w));
        __half2 o0 = __floats2half2_rn(f0.x + h[0], f0.y + h[1]);
        __half2 o1 = __floats2half2_rn(f1.x + h[2], f1.y + h[3]);
        __half2 o2 = __floats2half2_rn(f2.x + h[4], f2.y + h[5]);
        __half2 o3 = __floats2half2_rn(f3.x + h[6], f3.y + h[7]);
        fd.x = *reinterpret_cast<unsigned int*>(&o0);
        fd.y = *reinterpret_cast<unsigned int*>(&o1);
        fd.z = *reinterpret_cast<unsigned int*>(&o2);
        fd.w = *reinterpret_cast<unsigned int*>(&o3);
        *fp = fd;
        // acc (fp32): acc = (acc + h) * oscale
        float4* ap = reinterpret_cast<float4*>(acc) + (size_t)row * 32 + 2 * slot;
        float4 av0 = ap[0];
        float4 av1 = ap[1];
        av0.x = (av0.x + h[0]) * oscale;
        av0.y = (av0.y + h[1]) * oscale;
        av0.z = (av0.z + h[2]) * oscale;
        av0.w = (av0.w + h[3]) * oscale;
        av1.x = (av1.x + h[4]) * oscale;
        av1.y = (av1.y + h[5]) * oscale;
        av1.z = (av1.z + h[6]) * oscale;
        av1.w = (av1.w + h[7]) * oscale;
        ap[0] = av0;
        ap[1] = av1;
    }
}

__global__ void spmm_ln_dual(const int*  __restrict__ ptrA, const int2* __restrict__ edgeA,
                             const __half* __restrict__ xA,
                             const float* __restrict__ gA, const float* __restrict__ bA,
                             __half* __restrict__ featA, float* __restrict__ accA,
                             int nA, int blocksA,
                             const int*  __restrict__ ptrB, const int2* __restrict__ edgeB,
                             const __half* __restrict__ xB,
                             const float* __restrict__ gB, const float* __restrict__ bB,
                             __half* __restrict__ featB, float* __restrict__ accB,
                             int nB, float oscale) {
    if ((int)blockIdx.x < blocksA)
        spmm_ln_job(ptrA, edgeA, xA, gA, bA, featA, accA, nA, blockIdx.x, oscale);
    else
        spmm_ln_job(ptrB, edgeB, xB, gB, bB, featB, accB, nB, blockIdx.x - blocksA, oscale);
}

// ---------------- tensor-core GEMM (X @ W^T) + LayerNorm ---------------------
__device__ __forceinline__ void gemm_ln_mma_job(const __half* __restrict__ X,
                                                const __half* __restrict__ Wt,
                                                const float* __restrict__ g,
                                                const float* __restrict__ b,
                                                __half* __restrict__ out,
                                                int nrows, int bid, int nblocks,
                                                __half* sW, __half* sX) {
    const int tid  = threadIdx.x;
    const int w    = tid >> 5;
    const int lane = tid & 31;

    __shared__ float sSum[16][4];
    __shared__ float sSq [16][4];
    __shared__ float sMu [16];
    __shared__ float sRs [16];

    {
        const uint4* src = reinterpret_cast<const uint4*>(Wt);
        uint4* dst = reinterpret_cast<uint4*>(sW);
        const int n16 = D_H * WPITCH / 8;
        for (int i = tid; i < n16; i += 128) dst[i] = src[i];
    }
    __syncthreads();

    unsigned int bfr[8][4][2];
    {
        unsigned int swBase = (unsigned int)__cvta_generic_to_shared(sW);
        #pragma unroll
        for (int kc = 0; kc < 8; kc++) {
            #pragma unroll
            for (int ncl = 0; ncl < 4; ncl++) {
                int krow = kc * 16 + (lane & 15);
                int col  = w * 32 + ncl * 8;
                unsigned int addr = swBase + (unsigned int)((krow * WPITCH + col) * 2);
                asm volatile("ldmatrix.sync.aligned.m8n8.x2.trans.shared.b16 {%0,%1}, [%2];"
                             : "=r"(bfr[kc][ncl][0]), "=r"(bfr[kc][ncl][1]) : "r"(addr));
            }
        }
    }

    float2 gv[4], bv[4];
    #pragma unroll
    for (int ncl = 0; ncl < 4; ncl++) {
        int j = w * 32 + ncl * 8 + (lane & 3) * 2;
        gv[ncl] = *reinterpret_cast<const float2*>(g + j);
        bv[ncl] = *reinterpret_cast<const float2*>(b + j);
    }

    const int ntiles = (nrows + 15) >> 4;
    unsigned int sxBase = (unsigned int)__cvta_generic_to_shared(sX);

    for (int tile = bid; tile < ntiles; tile += nblocks) {
        const int rowbase = tile * 16;
        {
            int r = tid >> 3;
            int p = tid & 7;
            int grow = rowbase + r;
            uint4 z = make_uint4(0, 0, 0, 0);
            const uint4* xr = reinterpret_cast<const uint4*>(X) + (size_t)grow * 16;
            uint4* dst = reinterpret_cast<uint4*>(sX + r * WPITCH);
            if (grow < nrows) {
                dst[p]     = __ldg(xr + p);
                dst[p + 8] = __ldg(xr + p + 8);
            } else {
                dst[p] = z; dst[p + 8] = z;
            }
        }
        __syncthreads();

        float acc[4][4];
        #pragma unroll
        for (int ncl = 0; ncl < 4; ncl++)
            #pragma unroll
            for (int q = 0; q < 4; q++) acc[ncl][q] = 0.f;

        #pragma unroll
        for (int kc = 0; kc < 8; kc++) {
            unsigned int a0, a1, a2, a3;
            int arow = (lane & 7) + ((lane >> 3) & 1) * 8;
            int acol = kc * 16 + ((lane >> 4) & 1) * 8;
            unsigned int addr = sxBase + (unsigned int)((arow * WPITCH + acol) * 2);
            asm volatile("ldmatrix.sync.aligned.m8n8.x4.shared.b16 {%0,%1,%2,%3}, [%4];"
                         : "=r"(a0), "=r"(a1), "=r"(a2), "=r"(a3) : "r"(addr));
            #pragma unroll
            for (int ncl = 0; ncl < 4; ncl++) {
                asm volatile("mma.sync.aligned.m16n8k16.row.col.f32.f16.f16.f32 "
                             "{%0,%1,%2,%3}, {%4,%5,%6,%7}, {%8,%9}, {%0,%1,%2,%3};"
                             : "+f"(acc[ncl][0]), "+f"(acc[ncl][1]),
                               "+f"(acc[ncl][2]), "+f"(acc[ncl][3])
                             : "r"(a0), "r"(a1), "r"(a2), "r"(a3),
                               "r"(bfr[kc][ncl][0]), "r"(bfr[kc][ncl][1]));
            }
        }

        float s0 = 0.f, s1 = 0.f, q0 = 0.f, q1 = 0.f;
        #pragma unroll
        for (int ncl = 0; ncl < 4; ncl++) {
            s0 += acc[ncl][0] + acc[ncl][1];
            s1 += acc[ncl][2] + acc[ncl][3];
            q0 += acc[ncl][0] * acc[ncl][0] + acc[ncl][1] * acc[ncl][1];
            q1 += acc[ncl][2] * acc[ncl][2] + acc[ncl][3] * acc[ncl][3];
        }
        s0 += __shfl_xor_sync(0xffffffffu, s0, 1);
        s0 += __shfl_xor_sync(0xffffffffu, s0, 2);
        s1 += __shfl_xor_sync(0xffffffffu, s1, 1);
        s1 += __shfl_xor_sync(0xffffffffu, s1, 2);
        q0 += __shfl_xor_sync(0xffffffffu, q0, 1);
        q0 += __shfl_xor_sync(0xffffffffu, q0, 2);
        q1 += __shfl_xor_sync(0xffffffffu, q1, 1);
        q1 += __shfl_xor_sync(0xffffffffu, q1, 2);
        if ((lane & 3) == 0) {
            int r = lane >> 2;
            sSum[r][w] = s0; sSum[r + 8][w] = s1;
            sSq [r][w] = q0; sSq [r + 8][w] = q1;
        }
        __syncthreads();
        if (tid < 16) {
            float s = sSum[tid][0] + sSum[tid][1] + sSum[tid][2] + sSum[tid][3];
            float q = sSq[tid][0] + sSq[tid][1] + sSq[tid][2] + sSq[tid][3];
            float mu = s * (1.f / 128.f);
            float var = q * (1.f / 128.f) - mu * mu;
            sMu[tid] = mu;
            sRs[tid] = rsqrtf(var + EPS_F);
        }
        __syncthreads();

        {
            int r0 = lane >> 2;
            float mu0 = sMu[r0],     rs0 = sRs[r0];
            float mu1 = sMu[r0 + 8], rs1 = sRs[r0 + 8];
            int grow0 = rowbase + r0;
            int grow1 = rowbase + r0 + 8;
            #pragma unroll
            for (int ncl = 0; ncl < 4; ncl++) {
                int j = w * 32 + ncl * 8 + (lane & 3) * 2;
                if (grow0 < nrows) {
                    __half2 o = __floats2half2_rn(
                        (acc[ncl][0] - mu0) * rs0 * gv[ncl].x + bv[ncl].x,
                        (acc[ncl][1] - mu0) * rs0 * gv[ncl].y + bv[ncl].y);
                    *reinterpret_cast<__half2*>(out + (size_t)grow0 * D_H + j) = o;
                }
                if (grow1 < nrows) {
                    __half2 o = __floats2half2_rn(
                        (acc[ncl][2] - mu1) * rs1 * gv[ncl].x + bv[ncl].x,
                        (acc[ncl][3] - mu1) * rs1 * gv[ncl].y + bv[ncl].y);
                    *reinterpret_cast<__half2*>(out + (size_t)grow1 * D_H + j) = o;
                }
            }
        }
        __syncthreads();
    }
}

__global__ void gemm_ln_mma_dual(const __half* __restrict__ XA, const __half* __restrict__ WtA,
                                 const float* __restrict__ gA, const float* __restrict__ bA,
                                 __half* __restrict__ outA, int nA, int blocksA,
                                 const __half* __restrict__ XB, const __half* __restrict__ WtB,
                                 const float* __restrict__ gB, const float* __restrict__ bB,
                                 __half* __restrict__ outB, int nB, int blocksB) {
    extern __shared__ __half smem[];
    __half* sW = smem;
    __half* sX = smem + D_H * WPITCH;
    if ((int)blockIdx.x < blocksA)
        gemm_ln_mma_job(XA, WtA, gA, bA, outA, nA, blockIdx.x, blocksA, sW, sX);
    else
        gemm_ln_mma_job(XB, WtB, gB, bB, outB, nB, blockIdx.x - blocksA, blocksB, sW, sX);
}

// ---------------- launch ------------------------------------------------------
extern "C" void kernel_launch(void* const* d_in, const int* in_sizes, int n_in,
                              void* d_out, int out_size) {
    const float* emb     = (const float*)d_in[0];
    const float* fc_u_w  = (const float*)d_in[1];
    const float* fc_u_b  = (const float*)d_in[2];
    const float* fc_i_w  = (const float*)d_in[3];
    const float* fc_i_b  = (const float*)d_in[4];
    const float* vals    = (const float*)d_in[5];
    const float* Wu      = (const float*)d_in[6];
    const float* ln1g_u  = (const float*)d_in[7];
    const float* ln1b_u  = (const float*)d_in[8];
    const float* ln2g_u  = (const float*)d_in[9];
    const float* ln2b_u  = (const float*)d_in[10];
    const float* Wi      = (const float*)d_in[11];
    const float* ln1g_i  = (const float*)d_in[12];
    const float* ln1b_i  = (const float*)d_in[13];
    const float* ln2g_i  = (const float*)d_in[14];
    const float* ln2b_i  = (const float*)d_in[15];
    const int*   rows    = (const int*)d_in[16];
    const int*   cols    = (const int*)d_in[17];
    float* out = (float*)d_out;
    const int nnz = in_sizes[5];
    (void)n_in; (void)out_size;

    __half *hU, *hI, *xhU, *xhI, *lU, *lI, *Wt0;
    int *ptrU, *ptrI, *posU, *posI, *cntU, *cntI, *chU, *chI;
    int2 *edgeU, *edgeI;
    cudaGetSymbolAddress((void**)&hU, g_hU);
    cudaGetSymbolAddress((void**)&hI, g_hI);
    cudaGetSymbolAddress((void**)&xhU, g_xhU);
    cudaGetSymbolAddress((void**)&xhI, g_xhI);
    cudaGetSymbolAddress((void**)&lU, g_lU);
    cudaGetSymbolAddress((void**)&lI, g_lI);
    cudaGetSymbolAddress((void**)&Wt0, g_Wt);
    cudaGetSymbolAddress((void**)&ptrU, g_ptrU);
    cudaGetSymbolAddress((void**)&ptrI, g_ptrI);
    cudaGetSymbolAddress((void**)&posU, g_posU);
    cudaGetSymbolAddress((void**)&posI, g_posI);
    cudaGetSymbolAddress((void**)&cntU, g_cntU);
    cudaGetSymbolAddress((void**)&cntI, g_cntI);
    cudaGetSymbolAddress((void**)&chU, g_chunkU);
    cudaGetSymbolAddress((void**)&chI, g_chunkI);
    cudaGetSymbolAddress((void**)&edgeU, g_edgeU);
    cudaGetSymbolAddress((void**)&edgeI, g_edgeI);

    const int EB = (nnz + 255) / 256;
    const int NCHU = (N_U + CHUNK - 1) / CHUNK;
    const int NCHI = (N_I + CHUNK - 1) / CHUNK;
    const size_t GEMM_SMEM = (size_t)(D_H + 16) * WPITCH * sizeof(__half);

    float* accU = out;
    float* accI = out + (size_t)N_U * D_H;

    // -------- prep: zero counters; then hist || fc_u || fc_i fused --------
    zero_int2arr<<<256, 256>>>(cntU, N_U, cntI, N_I);
    prep_fused<<<HB + FU + FI, 128>>>(rows, cols, cntU, cntI, nnz,
                                      emb, fc_u_w, fc_u_b, fc_i_w, fc_i_b,
                                      hU, hI, accU, accI);
    wconvert_kernel<<<(4 * D_H * D_H + 255) / 256, 256>>>(Wu, Wi);

    // -------- scan + build --------
    scan_reduce_dual<<<NCHU + NCHI, 256>>>(cntU, chU, NCHU, cntI, chI);
    scan_offsets<<<1, 64>>>(chU, NCHU, chI, NCHI);
    scan_write_dual<<<NCHU + NCHI, CHUNK>>>(cntU, chU, ptrU, posU, NCHU,
                                            cntI, chI, ptrI, posI);
    build_both_kernel<<<EB, 256>>>(rows, cols, vals, posU, posI, edgeU, edgeI, nnz);

    const int SPU = (N_U + 7) / 8;
    const int SPI = (N_I + 7) / 8;
    const int GA = 512, GB = 1024;

    for (int k = 0; k < N_LAYERS; k++) {
        const __half* WtU_k = Wt0 + (size_t)k * WPITCH * D_H;
        const __half* WtI_k = Wt0 + (size_t)(2 + k) * WPITCH * D_H;
        const float oscale = (k == N_LAYERS - 1) ? (1.f / 3.f) : 1.f;

        // phase 1: xhI = A^T u  ||  xhU = A i   [fp16 out]
        spmm_h_dual<<<SPI + SPU, 256>>>(ptrI, edgeI, hU, xhI, N_I, SPI,
                                        ptrU, edgeU, hI, xhU, N_U);
        // phase 2: lI = LN(xhI Wu^T)  ||  lU = LN(xhU Wi^T)  [tensor cores]
        gemm_ln_mma_dual<<<GA + GB, 128, GEMM_SMEM>>>(
            xhI, WtU_k, ln1g_u + k * D_H, ln1b_u + k * D_H, lI, N_I, GA,
            xhU, WtI_k, ln1g_i + k * D_H, ln1b_i + k * D_H, lU, N_U, GB);
        // phase 3+4 fused: u-update from A lI  ||  i-update from A^T lU
        spmm_ln_dual<<<SPU + SPI, 256>>>(ptrU, edgeU, lI,
                                         ln2g_u + k * D_H, ln2b_u + k * D_H,
                                         hU, accU, N_U, SPU,
                                         ptrI, edgeI, lU,
                                         ln2g_i + k * D_H, ln2b_i + k * D_H,
                                         hI, accI, N_I, oscale);
    }
}